// round 12
// baseline (speedup 1.0000x reference)
#include <cuda_runtime.h>
#include <cstdint>

// QuietAttention, FA2-style register-resident P.
// TQ=64, TK=32, 128 threads (4 warps x 16 q-rows each), 3 CTAs/SM.
// Single-pass unnormalized softmax; bf16 hi/lo 3-split mma.sync.
// out [16,2048,128] fp32 then p_attn [16,2048,2049] fp32 in d_out.

#define BB 16
#define SS 2048
#define DD 128
#define SP1 2049
#define NTH 128
#define TQ 64
#define TK 32
#define PITCHB 272

#define OFF_QHI 0               // 64 x 272 = 17408
#define OFF_QLO 17408
#define OFF_KHI 34816           // 32 x 272 = 8704
#define OFF_KLO 43520
#define OFF_VHI 52224
#define OFF_VLO 60928
#define OFF_MB  69632           // u16 mbits[64][2] = 256 B
#define SMEM_TOTAL 69888

__device__ __forceinline__ uint32_t smem_u32(const void* p) {
    uint32_t a;
    asm("{ .reg .u64 t; cvta.to.shared.u64 t, %1; cvt.u32.u64 %0, t; }" : "=r"(a) : "l"(p));
    return a;
}
__device__ __forceinline__ void pf_l2(const void* p) {
    asm volatile("prefetch.global.L2 [%0];" :: "l"(p));
}
__device__ __forceinline__ void ldsm4(uint32_t* r, uint32_t addr) {
    asm volatile("ldmatrix.sync.aligned.m8n8.x4.shared.b16 {%0,%1,%2,%3}, [%4];"
                 : "=r"(r[0]), "=r"(r[1]), "=r"(r[2]), "=r"(r[3]) : "r"(addr));
}
__device__ __forceinline__ void ldsm4t(uint32_t* r, uint32_t addr) {
    asm volatile("ldmatrix.sync.aligned.m8n8.x4.trans.shared.b16 {%0,%1,%2,%3}, [%4];"
                 : "=r"(r[0]), "=r"(r[1]), "=r"(r[2]), "=r"(r[3]) : "r"(addr));
}
__device__ __forceinline__ void mma16816(float* c, const uint32_t* a, const uint32_t* b) {
    asm volatile("mma.sync.aligned.m16n8k16.row.col.f32.bf16.bf16.f32 "
                 "{%0,%1,%2,%3}, {%4,%5,%6,%7}, {%8,%9}, {%0,%1,%2,%3};"
                 : "+f"(c[0]), "+f"(c[1]), "+f"(c[2]), "+f"(c[3])
                 : "r"(a[0]), "r"(a[1]), "r"(a[2]), "r"(a[3]), "r"(b[0]), "r"(b[1]));
}
__device__ __forceinline__ void pack2(float a, float b, uint32_t& h, uint32_t& l) {
    uint32_t hh;
    asm("cvt.rn.bf16x2.f32 %0, %1, %2;" : "=r"(hh) : "f"(b), "f"(a));
    float ra = a - __uint_as_float(hh << 16);
    float rb = b - __uint_as_float(hh & 0xffff0000u);
    uint32_t ll;
    asm("cvt.rn.bf16x2.f32 %0, %1, %2;" : "=r"(ll) : "f"(rb), "f"(ra));
    h = hh; l = ll;
}

// ROWSxDD fp32 tile -> bf16 hi/lo smem (128 threads)
template<int ROWS>
__device__ __forceinline__ void cvt_tile(const float* __restrict__ src,
                                         char* hi, char* lo, int tid) {
#pragma unroll
    for (int it = 0; it < (ROWS * DD / 4) / NTH; ++it) {
        int n4  = tid + it * NTH;
        int row = n4 >> 5, c4 = (n4 & 31) << 2;
        float4 x = ((const float4*)src)[n4];
        uint32_t h0, l0, h1, l1;
        pack2(x.x, x.y, h0, l0);
        pack2(x.z, x.w, h1, l1);
        *(uint2*)(hi + row * PITCHB + c4 * 2) = make_uint2(h0, h1);
        *(uint2*)(lo + row * PITCHB + c4 * 2) = make_uint2(l0, l1);
    }
}

__global__ __launch_bounds__(NTH, 3)
void qa_fa2_kernel(const float* __restrict__ q,
                   const float* __restrict__ k,
                   const float* __restrict__ v,
                   const int* __restrict__ mask,
                   float* __restrict__ out,
                   float* __restrict__ p)
{
    extern __shared__ char smem[];
    const uint32_t sb = smem_u32(smem);
    const int tid = threadIdx.x;
    const int lane = tid & 31, wid = tid >> 5;
    const int g = lane >> 2, tg = lane & 3;
    const int b = blockIdx.y, qbase = blockIdx.x * TQ;

    const float* qb = q + ((size_t)b * SS + qbase) * DD;
    const float* kb = k + (size_t)b * SS * DD;
    const float* vb = v + (size_t)b * SS * DD;
    const int*   mk = mask + ((size_t)b * SS + qbase) * SS;
    float*       pb = p + ((size_t)b * SS + qbase) * SP1;
    float*       ob = out + ((size_t)b * SS + qbase) * DD;

    uint16_t* mb16 = (uint16_t*)(smem + OFF_MB);
    const uint32_t* mb32 = (const uint32_t*)(smem + OFF_MB);

    const uint32_t a_off = (uint32_t)((((lane >> 3) & 1) * 8 + (lane & 7)) * PITCHB + (lane >> 4) * 16);
    const uint32_t b_off = (uint32_t)(((lane >> 4) * 8 + (lane & 7)) * PITCHB + ((lane >> 3) & 1) * 16);

    const float scale = 0.08838834764831845f;   // 1/sqrt(128)
    const int r0 = wid * 16 + g;                 // this lane's first owned row

    // Q -> bf16 hi/lo smem (once)
    cvt_tile<TQ>(qb, smem + OFF_QHI, smem + OFF_QLO, tid);
    pf_l2((const char*)kb + tid * 128);
    pf_l2((const char*)vb + tid * 128);
    pf_l2((const char*)(mk + (size_t)(tid >> 1) * SS + (tid & 1) * 16));

    float emax0 = 0.0f, z0 = 0.0f, emax1 = 0.0f, z1 = 0.0f;

    float oacc[16][4];
#pragma unroll
    for (int nt = 0; nt < 16; ++nt)
#pragma unroll
        for (int e = 0; e < 4; ++e) oacc[nt][e] = 0.0f;

    // ================= 64 key tiles of 32 =================
    for (int kt = 0; kt < 64; ++kt) {
        __syncthreads();                       // prior PV done with V; mbits reads done
        cvt_tile<TK>(kb + (size_t)kt * TK * DD, smem + OFF_KHI, smem + OFF_KLO, tid);
        cvt_tile<TK>(vb + (size_t)kt * TK * DD, smem + OFF_VHI, smem + OFF_VLO, tid);
        {   // mask bit-pack: thread -> (row, 16-key half)
            const int row = tid >> 1, half = tid & 1;
            const int4* mp = (const int4*)(mk + (size_t)row * SS + kt * TK + half * 16);
            uint32_t bits = 0;
#pragma unroll
            for (int j = 0; j < 4; ++j) {
                int4 m4 = __ldcs(mp + j);
                bits |= (m4.x ? 1u : 0u) << (4 * j);
                bits |= (m4.y ? 1u : 0u) << (4 * j + 1);
                bits |= (m4.z ? 1u : 0u) << (4 * j + 2);
                bits |= (m4.w ? 1u : 0u) << (4 * j + 3);
            }
            mb16[row * 2 + half] = (uint16_t)bits;
        }
        __syncthreads();

        if (kt + 1 < 64) {
            pf_l2((const char*)(kb + (size_t)(kt + 1) * TK * DD) + tid * 128);
            pf_l2((const char*)(vb + (size_t)(kt + 1) * TK * DD) + tid * 128);
            pf_l2((const char*)(mk + (size_t)(tid >> 1) * SS + (kt + 1) * TK + (tid & 1) * 16));
        }

        // ---- S = Q K^T : warp tile 16q x 32k ----
        float sacc[4][4];
#pragma unroll
        for (int nt = 0; nt < 4; ++nt)
#pragma unroll
            for (int e = 0; e < 4; ++e) sacc[nt][e] = 0.0f;

#pragma unroll
        for (int ks = 0; ks < 8; ++ks) {
            uint32_t ah[4], al[4], bh[2][4], bl[2][4];
            {
                uint32_t ra = (uint32_t)((wid * 16) * PITCHB + ks * 32) + a_off;
                ldsm4(ah, sb + OFF_QHI + ra);
                ldsm4(al, sb + OFF_QLO + ra);
            }
#pragma unroll
            for (int kk = 0; kk < 2; ++kk) {
                uint32_t rb = (uint32_t)((kk * 16) * PITCHB + ks * 32) + b_off;
                ldsm4(bh[kk], sb + OFF_KHI + rb);
                ldsm4(bl[kk], sb + OFF_KLO + rb);
            }
#pragma unroll
            for (int nt = 0; nt < 4; ++nt)
                mma16816(sacc[nt], ah, &bh[nt >> 1][(nt & 1) * 2]);   // hh
#pragma unroll
            for (int nt = 0; nt < 4; ++nt)
                mma16816(sacc[nt], ah, &bl[nt >> 1][(nt & 1) * 2]);   // hl
#pragma unroll
            for (int nt = 0; nt < 4; ++nt)
                mma16816(sacc[nt], al, &bh[nt >> 1][(nt & 1) * 2]);   // lh
        }

        // ---- epilogue: e = exp(s) masked->0; stats; e-store; pack to regs ----
        const uint32_t mw0 = mb32[r0];
        const uint32_t mw1 = mb32[r0 + 8];
        uint32_t Phi[8], Plo[8];               // [rh*4 + nt]
#pragma unroll
        for (int nt = 0; nt < 4; ++nt) {
            int bit0 = nt * 8 + tg * 2;
            float s0 = sacc[nt][0] * scale;
            float s1 = sacc[nt][1] * scale;
            float s2 = sacc[nt][2] * scale;
            float s3 = sacc[nt][3] * scale;
            float e0 = ((mw0 >> bit0) & 1u)       ? __expf(s0) : 0.0f;
            float e1 = ((mw0 >> (bit0 + 1)) & 1u) ? __expf(s1) : 0.0f;
            float e2 = ((mw1 >> bit0) & 1u)       ? __expf(s2) : 0.0f;
            float e3 = ((mw1 >> (bit0 + 1)) & 1u) ? __expf(s3) : 0.0f;
            emax0 = fmaxf(emax0, fmaxf(e0, e1));  z0 += e0 + e1;
            emax1 = fmaxf(emax1, fmaxf(e2, e3));  z1 += e2 + e3;
            float* d0 = pb + (size_t)r0 * SP1 + 1 + kt * TK + nt * 8 + tg * 2;
            float* d1 = pb + (size_t)(r0 + 8) * SP1 + 1 + kt * TK + nt * 8 + tg * 2;
            __stcs(d0, e0);  __stcs(d0 + 1, e1);
            __stcs(d1, e2);  __stcs(d1 + 1, e3);
            pack2(e0, e1, Phi[nt],     Plo[nt]);
            pack2(e2, e3, Phi[4 + nt], Plo[4 + nt]);
        }

        // ---- O += P V : P in registers, V via ldsm4t ----
#pragma unroll
        for (int c = 0; c < 2; ++c) {          // 16-key chunks
            uint32_t afh[4] = {Phi[2 * c], Phi[4 + 2 * c], Phi[2 * c + 1], Phi[4 + 2 * c + 1]};
            uint32_t afl[4] = {Plo[2 * c], Plo[4 + 2 * c], Plo[2 * c + 1], Plo[4 + 2 * c + 1]};
#pragma unroll
            for (int ndp = 0; ndp < 4; ++ndp) {
                uint32_t bh0[4], bh1[4], bl0[4], bl1[4];
                uint32_t rb0 = (uint32_t)((c * 16) * PITCHB + (ndp * 32) * 2) + a_off;
                uint32_t rb1 = (uint32_t)((c * 16) * PITCHB + (ndp * 32 + 16) * 2) + a_off;
                ldsm4t(bh0, sb + OFF_VHI + rb0);
                ldsm4t(bh1, sb + OFF_VHI + rb1);
                ldsm4t(bl0, sb + OFF_VLO + rb0);
                ldsm4t(bl1, sb + OFF_VLO + rb1);
                // hh
                mma16816(oacc[4 * ndp + 0], afh, &bh0[0]);
                mma16816(oacc[4 * ndp + 1], afh, &bh0[2]);
                mma16816(oacc[4 * ndp + 2], afh, &bh1[0]);
                mma16816(oacc[4 * ndp + 3], afh, &bh1[2]);
                // hl
                mma16816(oacc[4 * ndp + 0], afh, &bl0[0]);
                mma16816(oacc[4 * ndp + 1], afh, &bl0[2]);
                mma16816(oacc[4 * ndp + 2], afh, &bl1[0]);
                mma16816(oacc[4 * ndp + 3], afh, &bl1[2]);
                // lh
                mma16816(oacc[4 * ndp + 0], afl, &bh0[0]);
                mma16816(oacc[4 * ndp + 1], afl, &bh0[2]);
                mma16816(oacc[4 * ndp + 2], afl, &bh1[0]);
                mma16816(oacc[4 * ndp + 3], afl, &bh1[2]);
            }
        }
    }

    // ---- finalize stats: reduce across tg (rows are warp-private) ----
#pragma unroll
    for (int off = 1; off <= 2; off <<= 1) {
        emax0 = fmaxf(emax0, __shfl_xor_sync(0xffffffffu, emax0, off));
        z0   += __shfl_xor_sync(0xffffffffu, z0, off);
        emax1 = fmaxf(emax1, __shfl_xor_sync(0xffffffffu, emax1, off));
        z1   += __shfl_xor_sync(0xffffffffu, z1, off);
    }
    const float inv0 = 1.0f / (emax0 + z0);     // denom = e^m + sum e^s
    const float inv1 = 1.0f / (emax1 + z1);

    if (tg == 0) {                              // sink column = 0 (exp(-1e9-m) == 0)
        pb[(size_t)r0 * SP1] = 0.0f;
        pb[(size_t)(r0 + 8) * SP1] = 0.0f;
    }

    // ---- write O (scaled by inv) ----
#pragma unroll
    for (int nt = 0; nt < 16; ++nt) {
        int col = nt * 8 + tg * 2;
        *(float2*)(ob + (size_t)r0 * DD + col) =
            make_float2(oacc[nt][0] * inv0, oacc[nt][1] * inv0);
        *(float2*)(ob + (size_t)(r0 + 8) * DD + col) =
            make_float2(oacc[nt][2] * inv1, oacc[nt][3] * inv1);
    }

    // ---- rescale p: warp handles its own 16 rows; inv via shfl ----
#pragma unroll 1
    for (int rr = 0; rr < 16; ++rr) {
        const int row = wid * 16 + rr;
        float iv = __shfl_sync(0xffffffffu, (rr < 8) ? inv0 : inv1, (rr & 7) << 2);
        float* ga = pb + (size_t)row * SP1 + 1;
        const int head = (4 - ((row * SP1 + 1) & 3)) & 3;
        if (lane < head) ga[lane] *= iv;
        const int body4 = (SS - head) >> 2;
        float4* g4 = (float4*)(ga + head);
#pragma unroll 4
        for (int c = lane; c < body4; c += 32) {
            float4 x = __ldcs(g4 + c);
            x.x *= iv; x.y *= iv; x.z *= iv; x.w *= iv;
            __stcs(g4 + c, x);
        }
        const int done = head + body4 * 4;
        if (lane < (SS - done)) ga[done + lane] *= iv;
    }
}

extern "C" void kernel_launch(void* const* d_in, const int* in_sizes, int n_in,
                              void* d_out, int out_size)
{
    const float* q    = (const float*)d_in[0];
    const float* k    = (const float*)d_in[1];
    const float* v    = (const float*)d_in[2];
    const int*   mask = (const int*)d_in[3];

    const long OUT_N = (long)BB * SS * DD;
    const long P_N   = (long)BB * SS * SP1;

    float* out = (float*)d_out;
    float* p   = ((long)out_size == P_N) ? out : out + OUT_N;

    cudaFuncSetAttribute(qa_fa2_kernel,
                         cudaFuncAttributeMaxDynamicSharedMemorySize, SMEM_TOTAL);
    dim3 grid(SS / TQ, BB);
    qa_fa2_kernel<<<grid, NTH, SMEM_TOTAL>>>(q, k, v, mask, out, p);
}

// round 13
// speedup vs baseline: 1.1407x; 1.1407x over previous
#include <cuda_runtime.h>
#include <cuda_fp16.h>
#include <cstdint>

// QuietAttention, single-pass unnormalized softmax, TQ=64/TK=64,
// 256 threads, 2 CTAs/SM (R11 structure). e staged as fp16 in __device__
// scratch (halves p-path traffic); scale folded into Q convert.
// out [16,2048,128] fp32 then p_attn [16,2048,2049] fp32 in d_out.

#define BB 16
#define SS 2048
#define DD 128
#define SP1 2049
#define NTH 256
#define TQ 64
#define TK 64
#define PITCHB 272
#define PITCHP 144

#define OFF_QHI 0
#define OFF_QLO 17408
#define OFF_KHI 34816           // after QK: P hi
#define OFF_KLO 52224           // after QK: P lo
#define OFF_VHI 69632
#define OFF_VLO 87040
#define OFF_MB  104448          // uint16 mbits[64][4]
#define OFF_RM  104960
#define OFF_RZ  105984
#define OFF_SI  107008
#define SMEM_TOTAL 107264

// fp16 staging for unnormalized e: 16*2048*2048 halves = 128 MiB
static __device__ __half2 e_scratch[33554432];

__device__ __forceinline__ uint32_t smem_u32(const void* p) {
    uint32_t a;
    asm("{ .reg .u64 t; cvta.to.shared.u64 t, %1; cvt.u32.u64 %0, t; }" : "=r"(a) : "l"(p));
    return a;
}
__device__ __forceinline__ void pf_l2(const void* p) {
    asm volatile("prefetch.global.L2 [%0];" :: "l"(p));
}
__device__ __forceinline__ void ldsm4(uint32_t* r, uint32_t addr) {
    asm volatile("ldmatrix.sync.aligned.m8n8.x4.shared.b16 {%0,%1,%2,%3}, [%4];"
                 : "=r"(r[0]), "=r"(r[1]), "=r"(r[2]), "=r"(r[3]) : "r"(addr));
}
__device__ __forceinline__ void ldsm4t(uint32_t* r, uint32_t addr) {
    asm volatile("ldmatrix.sync.aligned.m8n8.x4.trans.shared.b16 {%0,%1,%2,%3}, [%4];"
                 : "=r"(r[0]), "=r"(r[1]), "=r"(r[2]), "=r"(r[3]) : "r"(addr));
}
__device__ __forceinline__ void mma16816(float* c, const uint32_t* a, const uint32_t* b) {
    asm volatile("mma.sync.aligned.m16n8k16.row.col.f32.bf16.bf16.f32 "
                 "{%0,%1,%2,%3}, {%4,%5,%6,%7}, {%8,%9}, {%0,%1,%2,%3};"
                 : "+f"(c[0]), "+f"(c[1]), "+f"(c[2]), "+f"(c[3])
                 : "r"(a[0]), "r"(a[1]), "r"(a[2]), "r"(a[3]), "r"(b[0]), "r"(b[1]));
}
__device__ __forceinline__ void pack2(float a, float b, uint32_t& h, uint32_t& l) {
    uint32_t hh;
    asm("cvt.rn.bf16x2.f32 %0, %1, %2;" : "=r"(hh) : "f"(b), "f"(a));
    float ra = a - __uint_as_float(hh << 16);
    float rb = b - __uint_as_float(hh & 0xffff0000u);
    uint32_t ll;
    asm("cvt.rn.bf16x2.f32 %0, %1, %2;" : "=r"(ll) : "f"(rb), "f"(ra));
    h = hh; l = ll;
}

// 64x128 fp32 tile -> bf16 hi/lo smem; optional compile-time pre-scale
template<bool SCALED>
__device__ __forceinline__ void cvt_tile(const float* __restrict__ src,
                                         char* hi, char* lo, int tid) {
    const float mul = 0.08838834764831845f;   // 1/sqrt(128)
#pragma unroll
    for (int it = 0; it < 8; ++it) {
        int n4  = tid + it * NTH;
        int row = n4 >> 5, c4 = (n4 & 31) << 2;
        float4 x = ((const float4*)src)[n4];
        if (SCALED) { x.x *= mul; x.y *= mul; x.z *= mul; x.w *= mul; }
        uint32_t h0, l0, h1, l1;
        pack2(x.x, x.y, h0, l0);
        pack2(x.z, x.w, h1, l1);
        *(uint2*)(hi + row * PITCHB + c4 * 2) = make_uint2(h0, h1);
        *(uint2*)(lo + row * PITCHB + c4 * 2) = make_uint2(l0, l1);
    }
}

__global__ __launch_bounds__(NTH, 2)
void qa_sp7_kernel(const float* __restrict__ q,
                   const float* __restrict__ k,
                   const float* __restrict__ v,
                   const int* __restrict__ mask,
                   float* __restrict__ out,
                   float* __restrict__ p)
{
    extern __shared__ char smem[];
    const uint32_t sb = smem_u32(smem);
    const int tid = threadIdx.x;
    const int lane = tid & 31, wid = tid >> 5;
    const int g = lane >> 2, tg = lane & 3;
    const int warpM = wid >> 2, warpN = wid & 3;
    const int b = blockIdx.y, qbase = blockIdx.x * TQ;
    const int gq = b * SS + qbase;              // global q-row base

    const float* qb = q + (size_t)gq * DD;
    const float* kb = k + (size_t)b * SS * DD;
    const float* vb = v + (size_t)b * SS * DD;
    const int*   mk = mask + (size_t)gq * SS;
    float*       pb = p + (size_t)gq * SP1;
    float*       ob = out + (size_t)gq * DD;

    uint16_t* mbits = (uint16_t*)(smem + OFF_MB);
    float* redM = (float*)(smem + OFF_RM);
    float* redZ = (float*)(smem + OFF_RZ);
    float* sInv = (float*)(smem + OFF_SI);

    const uint32_t a_off  = (uint32_t)((((lane >> 3) & 1) * 8 + (lane & 7)) * PITCHB + (lane >> 4) * 16);
    const uint32_t b_off  = (uint32_t)(((lane >> 4) * 8 + (lane & 7)) * PITCHB + ((lane >> 3) & 1) * 16);
    const uint32_t a_offP = (uint32_t)((((lane >> 3) & 1) * 8 + (lane & 7)) * PITCHP + (lane >> 4) * 16);

    cvt_tile<true>(qb, smem + OFF_QHI, smem + OFF_QLO, tid);   // Q pre-scaled
    pf_l2((const char*)kb + tid * 128);
    pf_l2((const char*)vb + tid * 128);
    pf_l2((const char*)(mk + (size_t)(tid >> 2) * SS + (tid & 3) * 16));

    float emax_run[4], z_run[4];
#pragma unroll
    for (int i = 0; i < 4; ++i) { emax_run[i] = 0.0f; z_run[i] = 0.0f; }

    float oacc[2][4][4];
#pragma unroll
    for (int mt = 0; mt < 2; ++mt)
#pragma unroll
        for (int nt = 0; nt < 4; ++nt)
#pragma unroll
            for (int e = 0; e < 4; ++e) oacc[mt][nt][e] = 0.0f;

    for (int kt = 0; kt < 32; ++kt) {
        __syncthreads();                 // prior PV done with V & P smem
        cvt_tile<false>(kb + (size_t)kt * TK * DD, smem + OFF_KHI, smem + OFF_KLO, tid);
        {
            const int row = tid >> 2, cg = tid & 3;
            const int4* mp = (const int4*)(mk + (size_t)row * SS + kt * TK + cg * 16);
            uint32_t bits = 0;
#pragma unroll
            for (int j = 0; j < 4; ++j) {
                int4 m4 = __ldcs(mp + j);
                bits |= (m4.x ? 1u : 0u) << (4 * j);
                bits |= (m4.y ? 1u : 0u) << (4 * j + 1);
                bits |= (m4.z ? 1u : 0u) << (4 * j + 2);
                bits |= (m4.w ? 1u : 0u) << (4 * j + 3);
            }
            mbits[row * 4 + cg] = (uint16_t)bits;
        }
        __syncthreads();

        if (kt + 1 < 32) {
            pf_l2((const char*)(kb + (size_t)(kt + 1) * TK * DD) + tid * 128);
            pf_l2((const char*)(mk + (size_t)(tid >> 2) * SS + (kt + 1) * TK + (tid & 3) * 16));
        }

        // ---- S = Q K^T (pre-scaled): fragment reuse, split-outer order ----
        float sacc[2][2][4];
#pragma unroll
        for (int mt = 0; mt < 2; ++mt)
#pragma unroll
            for (int nt = 0; nt < 2; ++nt)
#pragma unroll
                for (int e = 0; e < 4; ++e) sacc[mt][nt][e] = 0.0f;

#pragma unroll
        for (int ks = 0; ks < 8; ++ks) {
            uint32_t ah[2][4], al[2][4], bh[4], bl[4];
#pragma unroll
            for (int mt = 0; mt < 2; ++mt) {
                uint32_t ra = (uint32_t)((warpM * 32 + mt * 16) * PITCHB + ks * 32) + a_off;
                ldsm4(ah[mt], sb + OFF_QHI + ra);
                ldsm4(al[mt], sb + OFF_QLO + ra);
            }
            {
                uint32_t rb = (uint32_t)((warpN * 16) * PITCHB + ks * 32) + b_off;
                ldsm4(bh, sb + OFF_KHI + rb);
                ldsm4(bl, sb + OFF_KLO + rb);
            }
#pragma unroll
            for (int mt = 0; mt < 2; ++mt)
#pragma unroll
                for (int nt = 0; nt < 2; ++nt)
                    mma16816(sacc[mt][nt], ah[mt], &bh[nt * 2]);   // hh
#pragma unroll
            for (int mt = 0; mt < 2; ++mt)
#pragma unroll
                for (int nt = 0; nt < 2; ++nt)
                    mma16816(sacc[mt][nt], ah[mt], &bl[nt * 2]);   // hl
#pragma unroll
            for (int mt = 0; mt < 2; ++mt)
#pragma unroll
                for (int nt = 0; nt < 2; ++nt)
                    mma16816(sacc[mt][nt], al[mt], &bh[nt * 2]);   // lh
        }

        // ---- epilogue: e = exp(s) masked->0; emax & Z; fp16 pairs to scratch ----
#pragma unroll
        for (int mt = 0; mt < 2; ++mt) {
#pragma unroll
            for (int rh = 0; rh < 2; ++rh) {
                const int i = mt * 2 + rh;
                const int row = warpM * 32 + mt * 16 + rh * 8 + g;
                const uint32_t mw = mbits[row * 4 + warpN];
                __half2* sdst = e_scratch +
                    (((size_t)(gq + row) * SS + kt * TK + warpN * 16 + tg * 2) >> 1);
#pragma unroll
                for (int nt = 0; nt < 2; ++nt) {
                    int bit = nt * 8 + tg * 2;
                    float e0 = ((mw >> bit) & 1u)       ? __expf(sacc[mt][nt][rh * 2])     : 0.0f;
                    float e1 = ((mw >> (bit + 1)) & 1u) ? __expf(sacc[mt][nt][rh * 2 + 1]) : 0.0f;
                    emax_run[i] = fmaxf(emax_run[i], fmaxf(e0, e1));
                    z_run[i] += e0 + e1;
                    sacc[mt][nt][rh * 2]     = e0;
                    sacc[mt][nt][rh * 2 + 1] = e1;
                    __half2 hv = __floats2half2_rn(e0, e1);
                    __stcs((uint32_t*)(sdst + nt * 4), *(uint32_t*)&hv);
                }
            }
        }

        __syncthreads();   // K smem reads done -> reuse as P
        // ---- pack P + V convert (mid slot) ----
        {
            char* phi = smem + OFF_KHI;
            char* plo = smem + OFF_KLO;
#pragma unroll
            for (int mt = 0; mt < 2; ++mt)
#pragma unroll
                for (int rh = 0; rh < 2; ++rh) {
                    const int row = warpM * 32 + mt * 16 + rh * 8 + g;
#pragma unroll
                    for (int nt = 0; nt < 2; ++nt) {
                        uint32_t h, l;
                        pack2(sacc[mt][nt][rh * 2], sacc[mt][nt][rh * 2 + 1], h, l);
                        const int col = warpN * 16 + nt * 8 + tg * 2;
                        *(uint32_t*)(phi + row * PITCHP + col * 2) = h;
                        *(uint32_t*)(plo + row * PITCHP + col * 2) = l;
                    }
                }
        }
        cvt_tile<false>(vb + (size_t)kt * TK * DD, smem + OFF_VHI, smem + OFF_VLO, tid);
        if (kt + 1 < 32)
            pf_l2((const char*)(vb + (size_t)(kt + 1) * TK * DD) + tid * 128);
        __syncthreads();

        // ---- O += P V: fragment reuse, split-outer ----
#pragma unroll
        for (int ks = 0; ks < 4; ++ks) {
            uint32_t ah[2][4], al[2][4], bh[2][4], bl[2][4];
#pragma unroll
            for (int mt = 0; mt < 2; ++mt) {
                uint32_t ra = (uint32_t)((warpM * 32 + mt * 16) * PITCHP + ks * 32) + a_offP;
                ldsm4(ah[mt], sb + OFF_KHI + ra);
                ldsm4(al[mt], sb + OFF_KLO + ra);
            }
#pragma unroll
            for (int n2 = 0; n2 < 2; ++n2) {
                uint32_t rb = (uint32_t)((ks * 16) * PITCHB + (warpN * 32 + n2 * 16) * 2) + a_off;
                ldsm4t(bh[n2], sb + OFF_VHI + rb);
                ldsm4t(bl[n2], sb + OFF_VLO + rb);
            }
#pragma unroll
            for (int mt = 0; mt < 2; ++mt)
#pragma unroll
                for (int nt = 0; nt < 4; ++nt)
                    mma16816(oacc[mt][nt], ah[mt], &bh[nt >> 1][(nt & 1) * 2]);  // hh
#pragma unroll
            for (int mt = 0; mt < 2; ++mt)
#pragma unroll
                for (int nt = 0; nt < 4; ++nt)
                    mma16816(oacc[mt][nt], ah[mt], &bl[nt >> 1][(nt & 1) * 2]);  // hl
#pragma unroll
            for (int mt = 0; mt < 2; ++mt)
#pragma unroll
                for (int nt = 0; nt < 4; ++nt)
                    mma16816(oacc[mt][nt], al[mt], &bh[nt >> 1][(nt & 1) * 2]);  // lh
        }
    }

    // ---- reduce emax (max) and Z (sum) ----
#pragma unroll
    for (int off = 1; off <= 2; off <<= 1) {
#pragma unroll
        for (int i = 0; i < 4; ++i) {
            emax_run[i] = fmaxf(emax_run[i], __shfl_xor_sync(0xffffffffu, emax_run[i], off));
            z_run[i] += __shfl_xor_sync(0xffffffffu, z_run[i], off);
        }
    }
    __syncthreads();
    if (tg == 0) {
#pragma unroll
        for (int i = 0; i < 4; ++i) {
            int row = warpM * 32 + (i >> 1) * 16 + (i & 1) * 8 + g;
            redM[warpN * 64 + row] = emax_run[i];
            redZ[warpN * 64 + row] = z_run[i];
        }
    }
    __syncthreads();
    if (tid < 64) {
        float em = redM[tid], z = redZ[tid];
#pragma unroll
        for (int w = 1; w < 4; ++w) {
            em = fmaxf(em, redM[w * 64 + tid]);
            z += redZ[w * 64 + tid];
        }
        float inv = 1.0f / (em + z);       // denom = e^m + sum e^s
        sInv[tid] = inv;
        pb[(size_t)tid * SP1] = 0.0f;      // sink: exp(-1e9 - m) == 0 in fp32
    }
    __syncthreads();

    // ---- write O (scaled) ----
#pragma unroll
    for (int mt = 0; mt < 2; ++mt)
#pragma unroll
        for (int rh = 0; rh < 2; ++rh) {
            int row = warpM * 32 + mt * 16 + rh * 8 + g;
            float inv = sInv[row];
#pragma unroll
            for (int nt = 0; nt < 4; ++nt) {
                int col = warpN * 32 + nt * 8 + tg * 2;
                float2 val = make_float2(oacc[mt][nt][rh * 2] * inv,
                                         oacc[mt][nt][rh * 2 + 1] * inv);
                *(float2*)(ob + (size_t)row * DD + col) = val;
            }
        }

    // ---- finalize p: read fp16 scratch, scale by inv, alignment-phased writes ----
#pragma unroll 1
    for (int rr = 0; rr < 8; ++rr) {
        const int row = wid * 8 + rr;
        const float iv = sInv[row];
        const uint4* src = (const uint4*)(e_scratch + ((size_t)(gq + row) * SS >> 1));
        float* ga = pb + (size_t)row * SP1 + 1;
        const int h = (3 - row) & 3;       // first 16B-aligned element offset
#pragma unroll 2
        for (int t = lane; t < 256; t += 32) {
            uint4 u = __ldcs(src + t);
            float2 f0 = __half22float2(*(__half2*)&u.x);
            float2 f1 = __half22float2(*(__half2*)&u.y);
            float2 f2 = __half22float2(*(__half2*)&u.z);
            float2 f3 = __half22float2(*(__half2*)&u.w);
            float v0 = f0.x * iv, v1 = f0.y * iv, v2 = f1.x * iv, v3 = f1.y * iv;
            float v4 = f2.x * iv, v5 = f2.y * iv, v6 = f3.x * iv, v7 = f3.y * iv;
            float* gp = ga + t * 8;
            if (h == 0) {
                *(float4*)gp       = make_float4(v0, v1, v2, v3);
                *(float4*)(gp + 4) = make_float4(v4, v5, v6, v7);
            } else if (h == 1) {
                gp[0] = v0;
                *(float4*)(gp + 1) = make_float4(v1, v2, v3, v4);
                *(float2*)(gp + 5) = make_float2(v5, v6);
                gp[7] = v7;
            } else if (h == 2) {
                *(float2*)gp       = make_float2(v0, v1);
                *(float4*)(gp + 2) = make_float4(v2, v3, v4, v5);
                *(float2*)(gp + 6) = make_float2(v6, v7);
            } else {
                gp[0] = v0;
                *(float2*)(gp + 1) = make_float2(v1, v2);
                *(float4*)(gp + 3) = make_float4(v3, v4, v5, v6);
                gp[7] = v7;
            }
        }
    }
}

extern "C" void kernel_launch(void* const* d_in, const int* in_sizes, int n_in,
                              void* d_out, int out_size)
{
    const float* q    = (const float*)d_in[0];
    const float* k    = (const float*)d_in[1];
    const float* v    = (const float*)d_in[2];
    const int*   mask = (const int*)d_in[3];

    const long OUT_N = (long)BB * SS * DD;
    const long P_N   = (long)BB * SS * SP1;

    float* out = (float*)d_out;
    float* p   = ((long)out_size == P_N) ? out : out + OUT_N;

    cudaFuncSetAttribute(qa_sp7_kernel,
                         cudaFuncAttributeMaxDynamicSharedMemorySize, SMEM_TOTAL);
    dim3 grid(SS / TQ, BB);
    qa_sp7_kernel<<<grid, NTH, SMEM_TOTAL>>>(q, k, v, mask, out, p);
}

// round 14
// speedup vs baseline: 1.2273x; 1.0759x over previous
#include <cuda_runtime.h>
#include <cuda_fp16.h>
#include <cstdint>

// QuietAttention, single-pass unnormalized softmax, TQ=64/TK=64,
// 256 threads, 2 CTAs/SM. QK: bf16 hi/lo 3-split. PV: fp16 P (single,
// bit-identical to staged output) x fp16 V hi/lo 2-split (f16 mma).
// e staged fp16 in __device__ scratch; scale folded into Q convert.
// out [16,2048,128] fp32 then p_attn [16,2048,2049] fp32 in d_out.

#define BB 16
#define SS 2048
#define DD 128
#define SP1 2049
#define NTH 256
#define TQ 64
#define TK 64
#define PITCHB 272
#define PITCHP 144

#define OFF_QHI 0
#define OFF_QLO 17408
#define OFF_KHI 34816           // after QK: P (fp16, single)
#define OFF_KLO 52224
#define OFF_VHI 69632
#define OFF_VLO 87040
#define OFF_MB  104448          // uint16 mbits[64][4]
#define OFF_RM  104960
#define OFF_RZ  105984
#define OFF_SI  107008
#define SMEM_TOTAL 107264

// fp16 staging for unnormalized e: 16*2048*2048 halves = 128 MiB
static __device__ __half2 e_scratch[33554432];

__device__ __forceinline__ uint32_t smem_u32(const void* p) {
    uint32_t a;
    asm("{ .reg .u64 t; cvta.to.shared.u64 t, %1; cvt.u32.u64 %0, t; }" : "=r"(a) : "l"(p));
    return a;
}
__device__ __forceinline__ void pf_l2(const void* p) {
    asm volatile("prefetch.global.L2 [%0];" :: "l"(p));
}
__device__ __forceinline__ void ldsm4(uint32_t* r, uint32_t addr) {
    asm volatile("ldmatrix.sync.aligned.m8n8.x4.shared.b16 {%0,%1,%2,%3}, [%4];"
                 : "=r"(r[0]), "=r"(r[1]), "=r"(r[2]), "=r"(r[3]) : "r"(addr));
}
__device__ __forceinline__ void ldsm4t(uint32_t* r, uint32_t addr) {
    asm volatile("ldmatrix.sync.aligned.m8n8.x4.trans.shared.b16 {%0,%1,%2,%3}, [%4];"
                 : "=r"(r[0]), "=r"(r[1]), "=r"(r[2]), "=r"(r[3]) : "r"(addr));
}
// bf16 mma (QK path)
__device__ __forceinline__ void mma_bf16(float* c, const uint32_t* a, const uint32_t* b) {
    asm volatile("mma.sync.aligned.m16n8k16.row.col.f32.bf16.bf16.f32 "
                 "{%0,%1,%2,%3}, {%4,%5,%6,%7}, {%8,%9}, {%0,%1,%2,%3};"
                 : "+f"(c[0]), "+f"(c[1]), "+f"(c[2]), "+f"(c[3])
                 : "r"(a[0]), "r"(a[1]), "r"(a[2]), "r"(a[3]), "r"(b[0]), "r"(b[1]));
}
// f16 mma (PV path)
__device__ __forceinline__ void mma_f16(float* c, const uint32_t* a, const uint32_t* b) {
    asm volatile("mma.sync.aligned.m16n8k16.row.col.f32.f16.f16.f32 "
                 "{%0,%1,%2,%3}, {%4,%5,%6,%7}, {%8,%9}, {%0,%1,%2,%3};"
                 : "+f"(c[0]), "+f"(c[1]), "+f"(c[2]), "+f"(c[3])
                 : "r"(a[0]), "r"(a[1]), "r"(a[2]), "r"(a[3]), "r"(b[0]), "r"(b[1]));
}
// bf16 hi/lo split (QK operands)
__device__ __forceinline__ void pack2(float a, float b, uint32_t& h, uint32_t& l) {
    uint32_t hh;
    asm("cvt.rn.bf16x2.f32 %0, %1, %2;" : "=r"(hh) : "f"(b), "f"(a));
    float ra = a - __uint_as_float(hh << 16);
    float rb = b - __uint_as_float(hh & 0xffff0000u);
    uint32_t ll;
    asm("cvt.rn.bf16x2.f32 %0, %1, %2;" : "=r"(ll) : "f"(rb), "f"(ra));
    h = hh; l = ll;
}
// fp16 hi/lo split (V operand)
__device__ __forceinline__ void pack2h(float a, float b, uint32_t& h, uint32_t& l) {
    __half2 hh = __floats2half2_rn(a, b);
    float2 hf = __half22float2(hh);
    __half2 ll = __floats2half2_rn(a - hf.x, b - hf.y);
    h = *(uint32_t*)&hh; l = *(uint32_t*)&ll;
}

// 64x128 fp32 tile -> bf16 hi/lo smem; optional pre-scale (QK operands)
template<bool SCALED>
__device__ __forceinline__ void cvt_tile(const float* __restrict__ src,
                                         char* hi, char* lo, int tid) {
    const float mul = 0.08838834764831845f;   // 1/sqrt(128)
#pragma unroll
    for (int it = 0; it < 8; ++it) {
        int n4  = tid + it * NTH;
        int row = n4 >> 5, c4 = (n4 & 31) << 2;
        float4 x = ((const float4*)src)[n4];
        if (SCALED) { x.x *= mul; x.y *= mul; x.z *= mul; x.w *= mul; }
        uint32_t h0, l0, h1, l1;
        pack2(x.x, x.y, h0, l0);
        pack2(x.z, x.w, h1, l1);
        *(uint2*)(hi + row * PITCHB + c4 * 2) = make_uint2(h0, h1);
        *(uint2*)(lo + row * PITCHB + c4 * 2) = make_uint2(l0, l1);
    }
}
// 64x128 fp32 tile -> fp16 hi/lo smem (V operand)
__device__ __forceinline__ void cvt_tile_h(const float* __restrict__ src,
                                           char* hi, char* lo, int tid) {
#pragma unroll
    for (int it = 0; it < 8; ++it) {
        int n4  = tid + it * NTH;
        int row = n4 >> 5, c4 = (n4 & 31) << 2;
        float4 x = ((const float4*)src)[n4];
        uint32_t h0, l0, h1, l1;
        pack2h(x.x, x.y, h0, l0);
        pack2h(x.z, x.w, h1, l1);
        *(uint2*)(hi + row * PITCHB + c4 * 2) = make_uint2(h0, h1);
        *(uint2*)(lo + row * PITCHB + c4 * 2) = make_uint2(l0, l1);
    }
}

__global__ __launch_bounds__(NTH, 2)
void qa_sp8_kernel(const float* __restrict__ q,
                   const float* __restrict__ k,
                   const float* __restrict__ v,
                   const int* __restrict__ mask,
                   float* __restrict__ out,
                   float* __restrict__ p)
{
    extern __shared__ char smem[];
    const uint32_t sb = smem_u32(smem);
    const int tid = threadIdx.x;
    const int lane = tid & 31, wid = tid >> 5;
    const int g = lane >> 2, tg = lane & 3;
    const int warpM = wid >> 2, warpN = wid & 3;
    const int b = blockIdx.y, qbase = blockIdx.x * TQ;
    const int gq = b * SS + qbase;

    const float* qb = q + (size_t)gq * DD;
    const float* kb = k + (size_t)b * SS * DD;
    const float* vb = v + (size_t)b * SS * DD;
    const int*   mk = mask + (size_t)gq * SS;
    float*       pb = p + (size_t)gq * SP1;
    float*       ob = out + (size_t)gq * DD;

    uint16_t* mbits = (uint16_t*)(smem + OFF_MB);
    float* redM = (float*)(smem + OFF_RM);
    float* redZ = (float*)(smem + OFF_RZ);
    float* sInv = (float*)(smem + OFF_SI);

    const uint32_t a_off  = (uint32_t)((((lane >> 3) & 1) * 8 + (lane & 7)) * PITCHB + (lane >> 4) * 16);
    const uint32_t b_off  = (uint32_t)(((lane >> 4) * 8 + (lane & 7)) * PITCHB + ((lane >> 3) & 1) * 16);
    const uint32_t a_offP = (uint32_t)((((lane >> 3) & 1) * 8 + (lane & 7)) * PITCHP + (lane >> 4) * 16);

    cvt_tile<true>(qb, smem + OFF_QHI, smem + OFF_QLO, tid);   // Q pre-scaled
    pf_l2((const char*)kb + tid * 128);
    pf_l2((const char*)vb + tid * 128);
    pf_l2((const char*)(mk + (size_t)(tid >> 2) * SS + (tid & 3) * 16));

    float emax_run[4], z_run[4];
#pragma unroll
    for (int i = 0; i < 4; ++i) { emax_run[i] = 0.0f; z_run[i] = 0.0f; }

    float oacc[2][4][4];
#pragma unroll
    for (int mt = 0; mt < 2; ++mt)
#pragma unroll
        for (int nt = 0; nt < 4; ++nt)
#pragma unroll
            for (int e = 0; e < 4; ++e) oacc[mt][nt][e] = 0.0f;

    for (int kt = 0; kt < 32; ++kt) {
        __syncthreads();
        cvt_tile<false>(kb + (size_t)kt * TK * DD, smem + OFF_KHI, smem + OFF_KLO, tid);
        {
            const int row = tid >> 2, cg = tid & 3;
            const int4* mp = (const int4*)(mk + (size_t)row * SS + kt * TK + cg * 16);
            uint32_t bits = 0;
#pragma unroll
            for (int j = 0; j < 4; ++j) {
                int4 m4 = __ldcs(mp + j);
                bits |= (m4.x ? 1u : 0u) << (4 * j);
                bits |= (m4.y ? 1u : 0u) << (4 * j + 1);
                bits |= (m4.z ? 1u : 0u) << (4 * j + 2);
                bits |= (m4.w ? 1u : 0u) << (4 * j + 3);
            }
            mbits[row * 4 + cg] = (uint16_t)bits;
        }
        __syncthreads();

        if (kt + 1 < 32) {
            pf_l2((const char*)(kb + (size_t)(kt + 1) * TK * DD) + tid * 128);
            pf_l2((const char*)(mk + (size_t)(tid >> 2) * SS + (kt + 1) * TK + (tid & 3) * 16));
        }

        // ---- S = Q K^T (pre-scaled): bf16 3-split, fragment reuse ----
        float sacc[2][2][4];
#pragma unroll
        for (int mt = 0; mt < 2; ++mt)
#pragma unroll
            for (int nt = 0; nt < 2; ++nt)
#pragma unroll
                for (int e = 0; e < 4; ++e) sacc[mt][nt][e] = 0.0f;

#pragma unroll
        for (int ks = 0; ks < 8; ++ks) {
            uint32_t ah[2][4], al[2][4], bh[4], bl[4];
#pragma unroll
            for (int mt = 0; mt < 2; ++mt) {
                uint32_t ra = (uint32_t)((warpM * 32 + mt * 16) * PITCHB + ks * 32) + a_off;
                ldsm4(ah[mt], sb + OFF_QHI + ra);
                ldsm4(al[mt], sb + OFF_QLO + ra);
            }
            {
                uint32_t rb = (uint32_t)((warpN * 16) * PITCHB + ks * 32) + b_off;
                ldsm4(bh, sb + OFF_KHI + rb);
                ldsm4(bl, sb + OFF_KLO + rb);
            }
#pragma unroll
            for (int mt = 0; mt < 2; ++mt)
#pragma unroll
                for (int nt = 0; nt < 2; ++nt)
                    mma_bf16(sacc[mt][nt], ah[mt], &bh[nt * 2]);   // hh
#pragma unroll
            for (int mt = 0; mt < 2; ++mt)
#pragma unroll
                for (int nt = 0; nt < 2; ++nt)
                    mma_bf16(sacc[mt][nt], ah[mt], &bl[nt * 2]);   // hl
#pragma unroll
            for (int mt = 0; mt < 2; ++mt)
#pragma unroll
                for (int nt = 0; nt < 2; ++nt)
                    mma_bf16(sacc[mt][nt], al[mt], &bh[nt * 2]);   // lh
        }

        // ---- epilogue: e = exp(s) masked->0; stats; fp16 to scratch ----
#pragma unroll
        for (int mt = 0; mt < 2; ++mt) {
#pragma unroll
            for (int rh = 0; rh < 2; ++rh) {
                const int i = mt * 2 + rh;
                const int row = warpM * 32 + mt * 16 + rh * 8 + g;
                const uint32_t mw = mbits[row * 4 + warpN];
                __half2* sdst = e_scratch +
                    (((size_t)(gq + row) * SS + kt * TK + warpN * 16 + tg * 2) >> 1);
#pragma unroll
                for (int nt = 0; nt < 2; ++nt) {
                    int bit = nt * 8 + tg * 2;
                    float e0 = ((mw >> bit) & 1u)       ? __expf(sacc[mt][nt][rh * 2])     : 0.0f;
                    float e1 = ((mw >> (bit + 1)) & 1u) ? __expf(sacc[mt][nt][rh * 2 + 1]) : 0.0f;
                    emax_run[i] = fmaxf(emax_run[i], fmaxf(e0, e1));
                    z_run[i] += e0 + e1;
                    sacc[mt][nt][rh * 2]     = e0;
                    sacc[mt][nt][rh * 2 + 1] = e1;
                    __half2 hv = __floats2half2_rn(e0, e1);
                    __stcs((uint32_t*)(sdst + nt * 4), *(uint32_t*)&hv);
                }
            }
        }

        __syncthreads();   // K smem reads done -> reuse as P (fp16, single)
        {
            char* pP = smem + OFF_KHI;
#pragma unroll
            for (int mt = 0; mt < 2; ++mt)
#pragma unroll
                for (int rh = 0; rh < 2; ++rh) {
                    const int row = warpM * 32 + mt * 16 + rh * 8 + g;
#pragma unroll
                    for (int nt = 0; nt < 2; ++nt) {
                        __half2 hv = __floats2half2_rn(sacc[mt][nt][rh * 2],
                                                       sacc[mt][nt][rh * 2 + 1]);
                        const int col = warpN * 16 + nt * 8 + tg * 2;
                        *(uint32_t*)(pP + row * PITCHP + col * 2) = *(uint32_t*)&hv;
                    }
                }
        }
        cvt_tile_h(vb + (size_t)kt * TK * DD, smem + OFF_VHI, smem + OFF_VLO, tid);
        if (kt + 1 < 32)
            pf_l2((const char*)(vb + (size_t)(kt + 1) * TK * DD) + tid * 128);
        __syncthreads();

        // ---- O += P V: fp16 P single x fp16 V hi/lo (2 splits) ----
#pragma unroll
        for (int ks = 0; ks < 4; ++ks) {
            uint32_t ap[2][4], bh[2][4], bl[2][4];
#pragma unroll
            for (int mt = 0; mt < 2; ++mt) {
                uint32_t ra = (uint32_t)((warpM * 32 + mt * 16) * PITCHP + ks * 32) + a_offP;
                ldsm4(ap[mt], sb + OFF_KHI + ra);
            }
#pragma unroll
            for (int n2 = 0; n2 < 2; ++n2) {
                uint32_t rb = (uint32_t)((ks * 16) * PITCHB + (warpN * 32 + n2 * 16) * 2) + a_off;
                ldsm4t(bh[n2], sb + OFF_VHI + rb);
                ldsm4t(bl[n2], sb + OFF_VLO + rb);
            }
#pragma unroll
            for (int mt = 0; mt < 2; ++mt)
#pragma unroll
                for (int nt = 0; nt < 4; ++nt)
                    mma_f16(oacc[mt][nt], ap[mt], &bh[nt >> 1][(nt & 1) * 2]);  // P*Vh
#pragma unroll
            for (int mt = 0; mt < 2; ++mt)
#pragma unroll
                for (int nt = 0; nt < 4; ++nt)
                    mma_f16(oacc[mt][nt], ap[mt], &bl[nt >> 1][(nt & 1) * 2]);  // P*Vl
        }
    }

    // ---- reduce emax (max) and Z (sum) ----
#pragma unroll
    for (int off = 1; off <= 2; off <<= 1) {
#pragma unroll
        for (int i = 0; i < 4; ++i) {
            emax_run[i] = fmaxf(emax_run[i], __shfl_xor_sync(0xffffffffu, emax_run[i], off));
            z_run[i] += __shfl_xor_sync(0xffffffffu, z_run[i], off);
        }
    }
    __syncthreads();
    if (tg == 0) {
#pragma unroll
        for (int i = 0; i < 4; ++i) {
            int row = warpM * 32 + (i >> 1) * 16 + (i & 1) * 8 + g;
            redM[warpN * 64 + row] = emax_run[i];
            redZ[warpN * 64 + row] = z_run[i];
        }
    }
    __syncthreads();
    if (tid < 64) {
        float em = redM[tid], z = redZ[tid];
#pragma unroll
        for (int w = 1; w < 4; ++w) {
            em = fmaxf(em, redM[w * 64 + tid]);
            z += redZ[w * 64 + tid];
        }
        float inv = 1.0f / (em + z);       // denom = e^m + sum e^s
        sInv[tid] = inv;
        pb[(size_t)tid * SP1] = 0.0f;      // sink: exp(-1e9 - m) == 0 in fp32
    }
    __syncthreads();

    // ---- write O (scaled) ----
#pragma unroll
    for (int mt = 0; mt < 2; ++mt)
#pragma unroll
        for (int rh = 0; rh < 2; ++rh) {
            int row = warpM * 32 + mt * 16 + rh * 8 + g;
            float inv = sInv[row];
#pragma unroll
            for (int nt = 0; nt < 4; ++nt) {
                int col = warpN * 32 + nt * 8 + tg * 2;
                float2 val = make_float2(oacc[mt][nt][rh * 2] * inv,
                                         oacc[mt][nt][rh * 2 + 1] * inv);
                *(float2*)(ob + (size_t)row * DD + col) = val;
            }
        }

    // ---- finalize p: read fp16 scratch, scale, alignment-phased writes ----
#pragma unroll 1
    for (int rr = 0; rr < 8; ++rr) {
        const int row = wid * 8 + rr;
        const float iv = sInv[row];
        const uint4* src = (const uint4*)(e_scratch + ((size_t)(gq + row) * SS >> 1));
        float* ga = pb + (size_t)row * SP1 + 1;
        const int h = (3 - row) & 3;
#pragma unroll 2
        for (int t = lane; t < 256; t += 32) {
            uint4 u = __ldcs(src + t);
            float2 f0 = __half22float2(*(__half2*)&u.x);
            float2 f1 = __half22float2(*(__half2*)&u.y);
            float2 f2 = __half22float2(*(__half2*)&u.z);
            float2 f3 = __half22float2(*(__half2*)&u.w);
            float v0 = f0.x * iv, v1 = f0.y * iv, v2 = f1.x * iv, v3 = f1.y * iv;
            float v4 = f2.x * iv, v5 = f2.y * iv, v6 = f3.x * iv, v7 = f3.y * iv;
            float* gp = ga + t * 8;
            if (h == 0) {
                *(float4*)gp       = make_float4(v0, v1, v2, v3);
                *(float4*)(gp + 4) = make_float4(v4, v5, v6, v7);
            } else if (h == 1) {
                gp[0] = v0;
                *(float4*)(gp + 1) = make_float4(v1, v2, v3, v4);
                *(float2*)(gp + 5) = make_float2(v5, v6);
                gp[7] = v7;
            } else if (h == 2) {
                *(float2*)gp       = make_float2(v0, v1);
                *(float4*)(gp + 2) = make_float4(v2, v3, v4, v5);
                *(float2*)(gp + 6) = make_float2(v6, v7);
            } else {
                gp[0] = v0;
                *(float2*)(gp + 1) = make_float2(v1, v2);
                *(float4*)(gp + 3) = make_float4(v3, v4, v5, v6);
                gp[7] = v7;
            }
        }
    }
}

extern "C" void kernel_launch(void* const* d_in, const int* in_sizes, int n_in,
                              void* d_out, int out_size)
{
    const float* q    = (const float*)d_in[0];
    const float* k    = (const float*)d_in[1];
    const float* v    = (const float*)d_in[2];
    const int*   mask = (const int*)d_in[3];

    const long OUT_N = (long)BB * SS * DD;
    const long P_N   = (long)BB * SS * SP1;

    float* out = (float*)d_out;
    float* p   = ((long)out_size == P_N) ? out : out + OUT_N;

    cudaFuncSetAttribute(qa_sp8_kernel,
                         cudaFuncAttributeMaxDynamicSharedMemorySize, SMEM_TOTAL);
    dim3 grid(SS / TQ, BB);
    qa_sp8_kernel<<<grid, NTH, SMEM_TOTAL>>>(q, k, v, mask, out, p);
}

// round 15
// speedup vs baseline: 1.2859x; 1.0477x over previous
#include <cuda_runtime.h>
#include <cuda_fp16.h>
#include <cstdint>

// QuietAttention, single-pass unnormalized softmax, TQ=64/TK=64,
// 256 threads, 2 CTAs/SM. QK: bf16 hi/lo 3-split. PV: fp16 P single x
// fp16 V hi/lo. e staged fp16 via coalesced P-smem->scratch copy
// (overlapped with PV). Wide (128b) converts.
// out [16,2048,128] fp32 then p_attn [16,2048,2049] fp32 in d_out.

#define BB 16
#define SS 2048
#define DD 128
#define SP1 2049
#define NTH 256
#define TQ 64
#define TK 64
#define PITCHB 272
#define PITCHP 144

#define OFF_QHI 0
#define OFF_QLO 17408
#define OFF_KHI 34816           // after QK: P (fp16, single)
#define OFF_KLO 52224
#define OFF_VHI 69632
#define OFF_VLO 87040
#define OFF_MB  104448          // uint16 mbits[64][4]
#define OFF_RM  104960
#define OFF_RZ  105984
#define OFF_SI  107008
#define SMEM_TOTAL 107264

// fp16 staging for unnormalized e: 16*2048*2048 halves = 128 MiB
static __device__ __half2 e_scratch[33554432];

__device__ __forceinline__ uint32_t smem_u32(const void* p) {
    uint32_t a;
    asm("{ .reg .u64 t; cvta.to.shared.u64 t, %1; cvt.u32.u64 %0, t; }" : "=r"(a) : "l"(p));
    return a;
}
__device__ __forceinline__ void pf_l2(const void* p) {
    asm volatile("prefetch.global.L2 [%0];" :: "l"(p));
}
__device__ __forceinline__ void ldsm4(uint32_t* r, uint32_t addr) {
    asm volatile("ldmatrix.sync.aligned.m8n8.x4.shared.b16 {%0,%1,%2,%3}, [%4];"
                 : "=r"(r[0]), "=r"(r[1]), "=r"(r[2]), "=r"(r[3]) : "r"(addr));
}
__device__ __forceinline__ void ldsm4t(uint32_t* r, uint32_t addr) {
    asm volatile("ldmatrix.sync.aligned.m8n8.x4.trans.shared.b16 {%0,%1,%2,%3}, [%4];"
                 : "=r"(r[0]), "=r"(r[1]), "=r"(r[2]), "=r"(r[3]) : "r"(addr));
}
__device__ __forceinline__ void mma_bf16(float* c, const uint32_t* a, const uint32_t* b) {
    asm volatile("mma.sync.aligned.m16n8k16.row.col.f32.bf16.bf16.f32 "
                 "{%0,%1,%2,%3}, {%4,%5,%6,%7}, {%8,%9}, {%0,%1,%2,%3};"
                 : "+f"(c[0]), "+f"(c[1]), "+f"(c[2]), "+f"(c[3])
                 : "r"(a[0]), "r"(a[1]), "r"(a[2]), "r"(a[3]), "r"(b[0]), "r"(b[1]));
}
__device__ __forceinline__ void mma_f16(float* c, const uint32_t* a, const uint32_t* b) {
    asm volatile("mma.sync.aligned.m16n8k16.row.col.f32.f16.f16.f32 "
                 "{%0,%1,%2,%3}, {%4,%5,%6,%7}, {%8,%9}, {%0,%1,%2,%3};"
                 : "+f"(c[0]), "+f"(c[1]), "+f"(c[2]), "+f"(c[3])
                 : "r"(a[0]), "r"(a[1]), "r"(a[2]), "r"(a[3]), "r"(b[0]), "r"(b[1]));
}
__device__ __forceinline__ void pack2(float a, float b, uint32_t& h, uint32_t& l) {
    uint32_t hh;
    asm("cvt.rn.bf16x2.f32 %0, %1, %2;" : "=r"(hh) : "f"(b), "f"(a));
    float ra = a - __uint_as_float(hh << 16);
    float rb = b - __uint_as_float(hh & 0xffff0000u);
    uint32_t ll;
    asm("cvt.rn.bf16x2.f32 %0, %1, %2;" : "=r"(ll) : "f"(rb), "f"(ra));
    h = hh; l = ll;
}
__device__ __forceinline__ void pack2h(float a, float b, uint32_t& h, uint32_t& l) {
    __half2 hh = __floats2half2_rn(a, b);
    float2 hf = __half22float2(hh);
    __half2 ll = __floats2half2_rn(a - hf.x, b - hf.y);
    h = *(uint32_t*)&hh; l = *(uint32_t*)&ll;
}

// 64x128 fp32 tile -> bf16 hi/lo smem; 8 floats/thread/iter, STS.128
template<bool SCALED>
__device__ __forceinline__ void cvt_tile(const float* __restrict__ src,
                                         char* hi, char* lo, int tid) {
    const float mul = 0.08838834764831845f;   // 1/sqrt(128)
#pragma unroll
    for (int it = 0; it < 4; ++it) {
        int n8  = tid + it * NTH;              // 8-float chunk index 0..1023
        int row = n8 >> 4, c8 = n8 & 15;
        float4 x0 = ((const float4*)src)[n8 * 2];
        float4 x1 = ((const float4*)src)[n8 * 2 + 1];
        if (SCALED) {
            x0.x *= mul; x0.y *= mul; x0.z *= mul; x0.w *= mul;
            x1.x *= mul; x1.y *= mul; x1.z *= mul; x1.w *= mul;
        }
        uint32_t h0, l0, h1, l1, h2, l2, h3, l3;
        pack2(x0.x, x0.y, h0, l0);
        pack2(x0.z, x0.w, h1, l1);
        pack2(x1.x, x1.y, h2, l2);
        pack2(x1.z, x1.w, h3, l3);
        *(uint4*)(hi + row * PITCHB + c8 * 16) = make_uint4(h0, h1, h2, h3);
        *(uint4*)(lo + row * PITCHB + c8 * 16) = make_uint4(l0, l1, l2, l3);
    }
}
// 64x128 fp32 tile -> fp16 hi/lo smem (V operand), STS.128
__device__ __forceinline__ void cvt_tile_h(const float* __restrict__ src,
                                           char* hi, char* lo, int tid) {
#pragma unroll
    for (int it = 0; it < 4; ++it) {
        int n8  = tid + it * NTH;
        int row = n8 >> 4, c8 = n8 & 15;
        float4 x0 = ((const float4*)src)[n8 * 2];
        float4 x1 = ((const float4*)src)[n8 * 2 + 1];
        uint32_t h0, l0, h1, l1, h2, l2, h3, l3;
        pack2h(x0.x, x0.y, h0, l0);
        pack2h(x0.z, x0.w, h1, l1);
        pack2h(x1.x, x1.y, h2, l2);
        pack2h(x1.z, x1.w, h3, l3);
        *(uint4*)(hi + row * PITCHB + c8 * 16) = make_uint4(h0, h1, h2, h3);
        *(uint4*)(lo + row * PITCHB + c8 * 16) = make_uint4(l0, l1, l2, l3);
    }
}

__global__ __launch_bounds__(NTH, 2)
void qa_sp9_kernel(const float* __restrict__ q,
                   const float* __restrict__ k,
                   const float* __restrict__ v,
                   const int* __restrict__ mask,
                   float* __restrict__ out,
                   float* __restrict__ p)
{
    extern __shared__ char smem[];
    const uint32_t sb = smem_u32(smem);
    const int tid = threadIdx.x;
    const int lane = tid & 31, wid = tid >> 5;
    const int g = lane >> 2, tg = lane & 3;
    const int warpM = wid >> 2, warpN = wid & 3;
    const int b = blockIdx.y, qbase = blockIdx.x * TQ;
    const int gq = b * SS + qbase;

    const float* qb = q + (size_t)gq * DD;
    const float* kb = k + (size_t)b * SS * DD;
    const float* vb = v + (size_t)b * SS * DD;
    const int*   mk = mask + (size_t)gq * SS;
    float*       pb = p + (size_t)gq * SP1;
    float*       ob = out + (size_t)gq * DD;

    uint16_t* mbits = (uint16_t*)(smem + OFF_MB);
    float* redM = (float*)(smem + OFF_RM);
    float* redZ = (float*)(smem + OFF_RZ);
    float* sInv = (float*)(smem + OFF_SI);

    const uint32_t a_off  = (uint32_t)((((lane >> 3) & 1) * 8 + (lane & 7)) * PITCHB + (lane >> 4) * 16);
    const uint32_t b_off  = (uint32_t)(((lane >> 4) * 8 + (lane & 7)) * PITCHB + ((lane >> 3) & 1) * 16);
    const uint32_t a_offP = (uint32_t)((((lane >> 3) & 1) * 8 + (lane & 7)) * PITCHP + (lane >> 4) * 16);

    cvt_tile<true>(qb, smem + OFF_QHI, smem + OFF_QLO, tid);   // Q pre-scaled
    pf_l2((const char*)kb + tid * 128);
    pf_l2((const char*)vb + tid * 128);
    pf_l2((const char*)(mk + (size_t)(tid >> 2) * SS + (tid & 3) * 16));

    float emax_run[4], z_run[4];
#pragma unroll
    for (int i = 0; i < 4; ++i) { emax_run[i] = 0.0f; z_run[i] = 0.0f; }

    float oacc[2][4][4];
#pragma unroll
    for (int mt = 0; mt < 2; ++mt)
#pragma unroll
        for (int nt = 0; nt < 4; ++nt)
#pragma unroll
            for (int e = 0; e < 4; ++e) oacc[mt][nt][e] = 0.0f;

    for (int kt = 0; kt < 32; ++kt) {
        __syncthreads();
        cvt_tile<false>(kb + (size_t)kt * TK * DD, smem + OFF_KHI, smem + OFF_KLO, tid);
        {
            const int row = tid >> 2, cg = tid & 3;
            const int4* mp = (const int4*)(mk + (size_t)row * SS + kt * TK + cg * 16);
            uint32_t bits = 0;
#pragma unroll
            for (int j = 0; j < 4; ++j) {
                int4 m4 = __ldcs(mp + j);
                bits |= (m4.x ? 1u : 0u) << (4 * j);
                bits |= (m4.y ? 1u : 0u) << (4 * j + 1);
                bits |= (m4.z ? 1u : 0u) << (4 * j + 2);
                bits |= (m4.w ? 1u : 0u) << (4 * j + 3);
            }
            mbits[row * 4 + cg] = (uint16_t)bits;
        }
        __syncthreads();

        if (kt + 1 < 32) {
            pf_l2((const char*)(kb + (size_t)(kt + 1) * TK * DD) + tid * 128);
            pf_l2((const char*)(mk + (size_t)(tid >> 2) * SS + (kt + 1) * TK + (tid & 3) * 16));
        }

        // ---- S = Q K^T (pre-scaled): bf16 3-split, fragment reuse ----
        float sacc[2][2][4];
#pragma unroll
        for (int mt = 0; mt < 2; ++mt)
#pragma unroll
            for (int nt = 0; nt < 2; ++nt)
#pragma unroll
                for (int e = 0; e < 4; ++e) sacc[mt][nt][e] = 0.0f;

#pragma unroll
        for (int ks = 0; ks < 8; ++ks) {
            uint32_t ah[2][4], al[2][4], bh[4], bl[4];
#pragma unroll
            for (int mt = 0; mt < 2; ++mt) {
                uint32_t ra = (uint32_t)((warpM * 32 + mt * 16) * PITCHB + ks * 32) + a_off;
                ldsm4(ah[mt], sb + OFF_QHI + ra);
                ldsm4(al[mt], sb + OFF_QLO + ra);
            }
            {
                uint32_t rb = (uint32_t)((warpN * 16) * PITCHB + ks * 32) + b_off;
                ldsm4(bh, sb + OFF_KHI + rb);
                ldsm4(bl, sb + OFF_KLO + rb);
            }
#pragma unroll
            for (int mt = 0; mt < 2; ++mt)
#pragma unroll
                for (int nt = 0; nt < 2; ++nt)
                    mma_bf16(sacc[mt][nt], ah[mt], &bh[nt * 2]);   // hh
#pragma unroll
            for (int mt = 0; mt < 2; ++mt)
#pragma unroll
                for (int nt = 0; nt < 2; ++nt)
                    mma_bf16(sacc[mt][nt], ah[mt], &bl[nt * 2]);   // hl
#pragma unroll
            for (int mt = 0; mt < 2; ++mt)
#pragma unroll
                for (int nt = 0; nt < 2; ++nt)
                    mma_bf16(sacc[mt][nt], al[mt], &bh[nt * 2]);   // lh
        }

        // ---- epilogue: e = exp(s) masked->0; stats only (no gmem store) ----
#pragma unroll
        for (int mt = 0; mt < 2; ++mt) {
#pragma unroll
            for (int rh = 0; rh < 2; ++rh) {
                const int i = mt * 2 + rh;
                const int row = warpM * 32 + mt * 16 + rh * 8 + g;
                const uint32_t mw = mbits[row * 4 + warpN];
#pragma unroll
                for (int nt = 0; nt < 2; ++nt) {
                    int bit = nt * 8 + tg * 2;
                    float e0 = ((mw >> bit) & 1u)       ? __expf(sacc[mt][nt][rh * 2])     : 0.0f;
                    float e1 = ((mw >> (bit + 1)) & 1u) ? __expf(sacc[mt][nt][rh * 2 + 1]) : 0.0f;
                    emax_run[i] = fmaxf(emax_run[i], fmaxf(e0, e1));
                    z_run[i] += e0 + e1;
                    sacc[mt][nt][rh * 2]     = e0;
                    sacc[mt][nt][rh * 2 + 1] = e1;
                }
            }
        }

        __syncthreads();   // K smem reads done -> reuse as P (fp16, single)
        {
            char* pP = smem + OFF_KHI;
#pragma unroll
            for (int mt = 0; mt < 2; ++mt)
#pragma unroll
                for (int rh = 0; rh < 2; ++rh) {
                    const int row = warpM * 32 + mt * 16 + rh * 8 + g;
#pragma unroll
                    for (int nt = 0; nt < 2; ++nt) {
                        __half2 hv = __floats2half2_rn(sacc[mt][nt][rh * 2],
                                                       sacc[mt][nt][rh * 2 + 1]);
                        const int col = warpN * 16 + nt * 8 + tg * 2;
                        *(uint32_t*)(pP + row * PITCHP + col * 2) = *(uint32_t*)&hv;
                    }
                }
        }
        cvt_tile_h(vb + (size_t)kt * TK * DD, smem + OFF_VHI, smem + OFF_VLO, tid);
        if (kt + 1 < 32)
            pf_l2((const char*)(vb + (size_t)(kt + 1) * TK * DD) + tid * 128);
        __syncthreads();

        // ---- coalesced P-smem -> scratch copy (overlaps PV; bit-identical e) ----
        {
            const char* pP = smem + OFF_KHI;
#pragma unroll
            for (int it2 = 0; it2 < 2; ++it2) {
                int n = tid + it2 * NTH;            // 0..511
                int row = n >> 3, ch = n & 7;       // 64 rows x 8 x 16B = 8 KB
                uint4 u = *(const uint4*)(pP + row * PITCHP + ch * 16);
                uint4* dst = (uint4*)(e_scratch + (size_t)(gq + row) * (SS / 2) + kt * (TK / 2)) + ch;
                __stcs(dst, u);
            }
        }

        // ---- O += P V: fp16 P single x fp16 V hi/lo ----
#pragma unroll
        for (int ks = 0; ks < 4; ++ks) {
            uint32_t ap[2][4], bh[2][4], bl[2][4];
#pragma unroll
            for (int mt = 0; mt < 2; ++mt) {
                uint32_t ra = (uint32_t)((warpM * 32 + mt * 16) * PITCHP + ks * 32) + a_offP;
                ldsm4(ap[mt], sb + OFF_KHI + ra);
            }
#pragma unroll
            for (int n2 = 0; n2 < 2; ++n2) {
                uint32_t rb = (uint32_t)((ks * 16) * PITCHB + (warpN * 32 + n2 * 16) * 2) + a_off;
                ldsm4t(bh[n2], sb + OFF_VHI + rb);
                ldsm4t(bl[n2], sb + OFF_VLO + rb);
            }
#pragma unroll
            for (int mt = 0; mt < 2; ++mt)
#pragma unroll
                for (int nt = 0; nt < 4; ++nt)
                    mma_f16(oacc[mt][nt], ap[mt], &bh[nt >> 1][(nt & 1) * 2]);  // P*Vh
#pragma unroll
            for (int mt = 0; mt < 2; ++mt)
#pragma unroll
                for (int nt = 0; nt < 4; ++nt)
                    mma_f16(oacc[mt][nt], ap[mt], &bl[nt >> 1][(nt & 1) * 2]);  // P*Vl
        }
    }

    // ---- reduce emax (max) and Z (sum) ----
#pragma unroll
    for (int off = 1; off <= 2; off <<= 1) {
#pragma unroll
        for (int i = 0; i < 4; ++i) {
            emax_run[i] = fmaxf(emax_run[i], __shfl_xor_sync(0xffffffffu, emax_run[i], off));
            z_run[i] += __shfl_xor_sync(0xffffffffu, z_run[i], off);
        }
    }
    __syncthreads();
    if (tg == 0) {
#pragma unroll
        for (int i = 0; i < 4; ++i) {
            int row = warpM * 32 + (i >> 1) * 16 + (i & 1) * 8 + g;
            redM[warpN * 64 + row] = emax_run[i];
            redZ[warpN * 64 + row] = z_run[i];
        }
    }
    __syncthreads();
    if (tid < 64) {
        float em = redM[tid], z = redZ[tid];
#pragma unroll
        for (int w = 1; w < 4; ++w) {
            em = fmaxf(em, redM[w * 64 + tid]);
            z += redZ[w * 64 + tid];
        }
        float inv = 1.0f / (em + z);       // denom = e^m + sum e^s
        sInv[tid] = inv;
        pb[(size_t)tid * SP1] = 0.0f;      // sink: exp(-1e9 - m) == 0 in fp32
    }
    __syncthreads();

    // ---- write O (scaled) ----
#pragma unroll
    for (int mt = 0; mt < 2; ++mt)
#pragma unroll
        for (int rh = 0; rh < 2; ++rh) {
            int row = warpM * 32 + mt * 16 + rh * 8 + g;
            float inv = sInv[row];
#pragma unroll
            for (int nt = 0; nt < 4; ++nt) {
                int col = warpN * 32 + nt * 8 + tg * 2;
                float2 val = make_float2(oacc[mt][nt][rh * 2] * inv,
                                         oacc[mt][nt][rh * 2 + 1] * inv);
                *(float2*)(ob + (size_t)row * DD + col) = val;
            }
        }

    // ---- finalize p: read fp16 scratch, scale, alignment-phased writes ----
#pragma unroll 1
    for (int rr = 0; rr < 8; ++rr) {
        const int row = wid * 8 + rr;
        const float iv = sInv[row];
        const uint4* src = (const uint4*)(e_scratch + ((size_t)(gq + row) * SS >> 1));
        float* ga = pb + (size_t)row * SP1 + 1;
        const int h = (3 - row) & 3;
#pragma unroll 2
        for (int t = lane; t < 256; t += 32) {
            uint4 u = __ldcs(src + t);
            float2 f0 = __half22float2(*(__half2*)&u.x);
            float2 f1 = __half22float2(*(__half2*)&u.y);
            float2 f2 = __half22float2(*(__half2*)&u.z);
            float2 f3 = __half22float2(*(__half2*)&u.w);
            float v0 = f0.x * iv, v1 = f0.y * iv, v2 = f1.x * iv, v3 = f1.y * iv;
            float v4 = f2.x * iv, v5 = f2.y * iv, v6 = f3.x * iv, v7 = f3.y * iv;
            float* gp = ga + t * 8;
            if (h == 0) {
                *(float4*)gp       = make_float4(v0, v1, v2, v3);
                *(float4*)(gp + 4) = make_float4(v4, v5, v6, v7);
            } else if (h == 1) {
                gp[0] = v0;
                *(float4*)(gp + 1) = make_float4(v1, v2, v3, v4);
                *(float2*)(gp + 5) = make_float2(v5, v6);
                gp[7] = v7;
            } else if (h == 2) {
                *(float2*)gp       = make_float2(v0, v1);
                *(float4*)(gp + 2) = make_float4(v2, v3, v4, v5);
                *(float2*)(gp + 6) = make_float2(v6, v7);
            } else {
                gp[0] = v0;
                *(float2*)(gp + 1) = make_float2(v1, v2);
                *(float4*)(gp + 3) = make_float4(v3, v4, v5, v6);
                gp[7] = v7;
            }
        }
    }
}

extern "C" void kernel_launch(void* const* d_in, const int* in_sizes, int n_in,
                              void* d_out, int out_size)
{
    const float* q    = (const float*)d_in[0];
    const float* k    = (const float*)d_in[1];
    const float* v    = (const float*)d_in[2];
    const int*   mask = (const int*)d_in[3];

    const long OUT_N = (long)BB * SS * DD;
    const long P_N   = (long)BB * SS * SP1;

    float* out = (float*)d_out;
    float* p   = ((long)out_size == P_N) ? out : out + OUT_N;

    cudaFuncSetAttribute(qa_sp9_kernel,
                         cudaFuncAttributeMaxDynamicSharedMemorySize, SMEM_TOTAL);
    dim3 grid(SS / TQ, BB);
    qa_sp9_kernel<<<grid, NTH, SMEM_TOTAL>>>(q, k, v, mask, out, p);
}

// round 16
// speedup vs baseline: 1.4008x; 1.0893x over previous
#include <cuda_runtime.h>
#include <cuda_fp16.h>
#include <cstdint>

// QuietAttention, single-pass unnormalized softmax, TQ=64/TK=64,
// 256 threads, 2 CTAs/SM. QK: bf16 hi/lo 3-split. PV: fp16 P x fp16 V
// (both single). e staged fp16 via coalesced P-smem->scratch copy.
// out [16,2048,128] fp32 then p_attn [16,2048,2049] fp32 in d_out.

#define BB 16
#define SS 2048
#define DD 128
#define SP1 2049
#define NTH 256
#define TQ 64
#define TK 64
#define PITCHB 272
#define PITCHP 144

#define OFF_QHI 0
#define OFF_QLO 17408
#define OFF_KHI 34816           // after QK: P (fp16, single)
#define OFF_KLO 52224
#define OFF_VHI 69632           // V fp16 single
#define OFF_MB  87040           // uint16 mbits[64][4] = 512
#define OFF_RM  87552
#define OFF_RZ  88576
#define OFF_SI  89600
#define SMEM_TOTAL 89856

// fp16 staging for unnormalized e: 16*2048*2048 halves = 128 MiB
static __device__ __half2 e_scratch[33554432];

__device__ __forceinline__ uint32_t smem_u32(const void* p) {
    uint32_t a;
    asm("{ .reg .u64 t; cvta.to.shared.u64 t, %1; cvt.u32.u64 %0, t; }" : "=r"(a) : "l"(p));
    return a;
}
__device__ __forceinline__ void pf_l2(const void* p) {
    asm volatile("prefetch.global.L2 [%0];" :: "l"(p));
}
__device__ __forceinline__ void ldsm4(uint32_t* r, uint32_t addr) {
    asm volatile("ldmatrix.sync.aligned.m8n8.x4.shared.b16 {%0,%1,%2,%3}, [%4];"
                 : "=r"(r[0]), "=r"(r[1]), "=r"(r[2]), "=r"(r[3]) : "r"(addr));
}
__device__ __forceinline__ void ldsm4t(uint32_t* r, uint32_t addr) {
    asm volatile("ldmatrix.sync.aligned.m8n8.x4.trans.shared.b16 {%0,%1,%2,%3}, [%4];"
                 : "=r"(r[0]), "=r"(r[1]), "=r"(r[2]), "=r"(r[3]) : "r"(addr));
}
__device__ __forceinline__ void mma_bf16(float* c, const uint32_t* a, const uint32_t* b) {
    asm volatile("mma.sync.aligned.m16n8k16.row.col.f32.bf16.bf16.f32 "
                 "{%0,%1,%2,%3}, {%4,%5,%6,%7}, {%8,%9}, {%0,%1,%2,%3};"
                 : "+f"(c[0]), "+f"(c[1]), "+f"(c[2]), "+f"(c[3])
                 : "r"(a[0]), "r"(a[1]), "r"(a[2]), "r"(a[3]), "r"(b[0]), "r"(b[1]));
}
__device__ __forceinline__ void mma_f16(float* c, const uint32_t* a, const uint32_t* b) {
    asm volatile("mma.sync.aligned.m16n8k16.row.col.f32.f16.f16.f32 "
                 "{%0,%1,%2,%3}, {%4,%5,%6,%7}, {%8,%9}, {%0,%1,%2,%3};"
                 : "+f"(c[0]), "+f"(c[1]), "+f"(c[2]), "+f"(c[3])
                 : "r"(a[0]), "r"(a[1]), "r"(a[2]), "r"(a[3]), "r"(b[0]), "r"(b[1]));
}
__device__ __forceinline__ void pack2(float a, float b, uint32_t& h, uint32_t& l) {
    uint32_t hh;
    asm("cvt.rn.bf16x2.f32 %0, %1, %2;" : "=r"(hh) : "f"(b), "f"(a));
    float ra = a - __uint_as_float(hh << 16);
    float rb = b - __uint_as_float(hh & 0xffff0000u);
    uint32_t ll;
    asm("cvt.rn.bf16x2.f32 %0, %1, %2;" : "=r"(ll) : "f"(rb), "f"(ra));
    h = hh; l = ll;
}

// 64x128 fp32 tile -> bf16 hi/lo smem; 8 floats/thread/iter, STS.128
template<bool SCALED>
__device__ __forceinline__ void cvt_tile(const float* __restrict__ src,
                                         char* hi, char* lo, int tid) {
    const float mul = 0.08838834764831845f;   // 1/sqrt(128)
#pragma unroll
    for (int it = 0; it < 4; ++it) {
        int n8  = tid + it * NTH;
        int row = n8 >> 4, c8 = n8 & 15;
        float4 x0 = ((const float4*)src)[n8 * 2];
        float4 x1 = ((const float4*)src)[n8 * 2 + 1];
        if (SCALED) {
            x0.x *= mul; x0.y *= mul; x0.z *= mul; x0.w *= mul;
            x1.x *= mul; x1.y *= mul; x1.z *= mul; x1.w *= mul;
        }
        uint32_t h0, l0, h1, l1, h2, l2, h3, l3;
        pack2(x0.x, x0.y, h0, l0);
        pack2(x0.z, x0.w, h1, l1);
        pack2(x1.x, x1.y, h2, l2);
        pack2(x1.z, x1.w, h3, l3);
        *(uint4*)(hi + row * PITCHB + c8 * 16) = make_uint4(h0, h1, h2, h3);
        *(uint4*)(lo + row * PITCHB + c8 * 16) = make_uint4(l0, l1, l2, l3);
    }
}
// 64x128 fp32 tile -> fp16 single smem (V operand), STS.128
__device__ __forceinline__ void cvt_tile_h1(const float* __restrict__ src,
                                            char* hi, int tid) {
#pragma unroll
    for (int it = 0; it < 4; ++it) {
        int n8  = tid + it * NTH;
        int row = n8 >> 4, c8 = n8 & 15;
        float4 x0 = ((const float4*)src)[n8 * 2];
        float4 x1 = ((const float4*)src)[n8 * 2 + 1];
        __half2 p0 = __floats2half2_rn(x0.x, x0.y);
        __half2 p1 = __floats2half2_rn(x0.z, x0.w);
        __half2 p2 = __floats2half2_rn(x1.x, x1.y);
        __half2 p3 = __floats2half2_rn(x1.z, x1.w);
        *(uint4*)(hi + row * PITCHB + c8 * 16) =
            make_uint4(*(uint32_t*)&p0, *(uint32_t*)&p1, *(uint32_t*)&p2, *(uint32_t*)&p3);
    }
}

__global__ __launch_bounds__(NTH, 2)
void qa_spA_kernel(const float* __restrict__ q,
                   const float* __restrict__ k,
                   const float* __restrict__ v,
                   const int* __restrict__ mask,
                   float* __restrict__ out,
                   float* __restrict__ p)
{
    extern __shared__ char smem[];
    const uint32_t sb = smem_u32(smem);
    const int tid = threadIdx.x;
    const int lane = tid & 31, wid = tid >> 5;
    const int g = lane >> 2, tg = lane & 3;
    const int warpM = wid >> 2, warpN = wid & 3;
    const int b = blockIdx.y, qbase = blockIdx.x * TQ;
    const int gq = b * SS + qbase;

    const float* qb = q + (size_t)gq * DD;
    const float* kb = k + (size_t)b * SS * DD;
    const float* vb = v + (size_t)b * SS * DD;
    const int*   mk = mask + (size_t)gq * SS;
    float*       pb = p + (size_t)gq * SP1;
    float*       ob = out + (size_t)gq * DD;

    uint16_t* mbits = (uint16_t*)(smem + OFF_MB);
    float* redM = (float*)(smem + OFF_RM);
    float* redZ = (float*)(smem + OFF_RZ);
    float* sInv = (float*)(smem + OFF_SI);

    const uint32_t a_off  = (uint32_t)((((lane >> 3) & 1) * 8 + (lane & 7)) * PITCHB + (lane >> 4) * 16);
    const uint32_t b_off  = (uint32_t)(((lane >> 4) * 8 + (lane & 7)) * PITCHB + ((lane >> 3) & 1) * 16);
    const uint32_t a_offP = (uint32_t)((((lane >> 3) & 1) * 8 + (lane & 7)) * PITCHP + (lane >> 4) * 16);

    cvt_tile<true>(qb, smem + OFF_QHI, smem + OFF_QLO, tid);   // Q pre-scaled
    pf_l2((const char*)kb + tid * 128);
    pf_l2((const char*)vb + tid * 128);
    pf_l2((const char*)(mk + (size_t)(tid >> 2) * SS + (tid & 3) * 16));

    float emax_run[4], z_run[4];
#pragma unroll
    for (int i = 0; i < 4; ++i) { emax_run[i] = 0.0f; z_run[i] = 0.0f; }

    float oacc[2][4][4];
#pragma unroll
    for (int mt = 0; mt < 2; ++mt)
#pragma unroll
        for (int nt = 0; nt < 4; ++nt)
#pragma unroll
            for (int e = 0; e < 4; ++e) oacc[mt][nt][e] = 0.0f;

    for (int kt = 0; kt < 32; ++kt) {
        __syncthreads();
        cvt_tile<false>(kb + (size_t)kt * TK * DD, smem + OFF_KHI, smem + OFF_KLO, tid);
        {
            const int row = tid >> 2, cg = tid & 3;
            const int4* mp = (const int4*)(mk + (size_t)row * SS + kt * TK + cg * 16);
            uint32_t bits = 0;
#pragma unroll
            for (int j = 0; j < 4; ++j) {
                int4 m4 = __ldcs(mp + j);
                bits |= (m4.x ? 1u : 0u) << (4 * j);
                bits |= (m4.y ? 1u : 0u) << (4 * j + 1);
                bits |= (m4.z ? 1u : 0u) << (4 * j + 2);
                bits |= (m4.w ? 1u : 0u) << (4 * j + 3);
            }
            mbits[row * 4 + cg] = (uint16_t)bits;
        }
        __syncthreads();

        if (kt + 1 < 32) {
            pf_l2((const char*)(kb + (size_t)(kt + 1) * TK * DD) + tid * 128);
            pf_l2((const char*)(mk + (size_t)(tid >> 2) * SS + (kt + 1) * TK + (tid & 3) * 16));
        }

        // ---- S = Q K^T (pre-scaled): bf16 3-split, fragment reuse ----
        float sacc[2][2][4];
#pragma unroll
        for (int mt = 0; mt < 2; ++mt)
#pragma unroll
            for (int nt = 0; nt < 2; ++nt)
#pragma unroll
                for (int e = 0; e < 4; ++e) sacc[mt][nt][e] = 0.0f;

#pragma unroll
        for (int ks = 0; ks < 8; ++ks) {
            uint32_t ah[2][4], al[2][4], bh[4], bl[4];
#pragma unroll
            for (int mt = 0; mt < 2; ++mt) {
                uint32_t ra = (uint32_t)((warpM * 32 + mt * 16) * PITCHB + ks * 32) + a_off;
                ldsm4(ah[mt], sb + OFF_QHI + ra);
                ldsm4(al[mt], sb + OFF_QLO + ra);
            }
            {
                uint32_t rb = (uint32_t)((warpN * 16) * PITCHB + ks * 32) + b_off;
                ldsm4(bh, sb + OFF_KHI + rb);
                ldsm4(bl, sb + OFF_KLO + rb);
            }
#pragma unroll
            for (int mt = 0; mt < 2; ++mt)
#pragma unroll
                for (int nt = 0; nt < 2; ++nt)
                    mma_bf16(sacc[mt][nt], ah[mt], &bh[nt * 2]);   // hh
#pragma unroll
            for (int mt = 0; mt < 2; ++mt)
#pragma unroll
                for (int nt = 0; nt < 2; ++nt)
                    mma_bf16(sacc[mt][nt], ah[mt], &bl[nt * 2]);   // hl
#pragma unroll
            for (int mt = 0; mt < 2; ++mt)
#pragma unroll
                for (int nt = 0; nt < 2; ++nt)
                    mma_bf16(sacc[mt][nt], al[mt], &bh[nt * 2]);   // lh
        }

        // ---- epilogue: e = exp(s) masked->0; stats only ----
#pragma unroll
        for (int mt = 0; mt < 2; ++mt) {
#pragma unroll
            for (int rh = 0; rh < 2; ++rh) {
                const int i = mt * 2 + rh;
                const int row = warpM * 32 + mt * 16 + rh * 8 + g;
                const uint32_t mw = mbits[row * 4 + warpN];
#pragma unroll
                for (int nt = 0; nt < 2; ++nt) {
                    int bit = nt * 8 + tg * 2;
                    float e0 = ((mw >> bit) & 1u)       ? __expf(sacc[mt][nt][rh * 2])     : 0.0f;
                    float e1 = ((mw >> (bit + 1)) & 1u) ? __expf(sacc[mt][nt][rh * 2 + 1]) : 0.0f;
                    emax_run[i] = fmaxf(emax_run[i], fmaxf(e0, e1));
                    z_run[i] += e0 + e1;
                    sacc[mt][nt][rh * 2]     = e0;
                    sacc[mt][nt][rh * 2 + 1] = e1;
                }
            }
        }

        __syncthreads();   // K smem reads done -> reuse as P (fp16, single)
        {
            char* pP = smem + OFF_KHI;
#pragma unroll
            for (int mt = 0; mt < 2; ++mt)
#pragma unroll
                for (int rh = 0; rh < 2; ++rh) {
                    const int row = warpM * 32 + mt * 16 + rh * 8 + g;
#pragma unroll
                    for (int nt = 0; nt < 2; ++nt) {
                        __half2 hv = __floats2half2_rn(sacc[mt][nt][rh * 2],
                                                       sacc[mt][nt][rh * 2 + 1]);
                        const int col = warpN * 16 + nt * 8 + tg * 2;
                        *(uint32_t*)(pP + row * PITCHP + col * 2) = *(uint32_t*)&hv;
                    }
                }
        }
        cvt_tile_h1(vb + (size_t)kt * TK * DD, smem + OFF_VHI, tid);
        if (kt + 1 < 32)
            pf_l2((const char*)(vb + (size_t)(kt + 1) * TK * DD) + tid * 128);
        __syncthreads();

        // ---- coalesced P-smem -> scratch copy (overlaps PV) ----
        {
            const char* pP = smem + OFF_KHI;
#pragma unroll
            for (int it2 = 0; it2 < 2; ++it2) {
                int n = tid + it2 * NTH;
                int row = n >> 3, ch = n & 7;
                uint4 u = *(const uint4*)(pP + row * PITCHP + ch * 16);
                uint4* dst = (uint4*)(e_scratch + (size_t)(gq + row) * (SS / 2) + kt * (TK / 2)) + ch;
                __stcs(dst, u);
            }
        }

        // ---- O += P V: fp16 P single x fp16 V single ----
#pragma unroll
        for (int ks = 0; ks < 4; ++ks) {
            uint32_t ap[2][4], bh[2][4];
#pragma unroll
            for (int mt = 0; mt < 2; ++mt) {
                uint32_t ra = (uint32_t)((warpM * 32 + mt * 16) * PITCHP + ks * 32) + a_offP;
                ldsm4(ap[mt], sb + OFF_KHI + ra);
            }
#pragma unroll
            for (int n2 = 0; n2 < 2; ++n2) {
                uint32_t rb = (uint32_t)((ks * 16) * PITCHB + (warpN * 32 + n2 * 16) * 2) + a_off;
                ldsm4t(bh[n2], sb + OFF_VHI + rb);
            }
#pragma unroll
            for (int mt = 0; mt < 2; ++mt)
#pragma unroll
                for (int nt = 0; nt < 4; ++nt)
                    mma_f16(oacc[mt][nt], ap[mt], &bh[nt >> 1][(nt & 1) * 2]);
        }
    }

    // ---- reduce emax (max) and Z (sum) ----
#pragma unroll
    for (int off = 1; off <= 2; off <<= 1) {
#pragma unroll
        for (int i = 0; i < 4; ++i) {
            emax_run[i] = fmaxf(emax_run[i], __shfl_xor_sync(0xffffffffu, emax_run[i], off));
            z_run[i] += __shfl_xor_sync(0xffffffffu, z_run[i], off);
        }
    }
    __syncthreads();
    if (tg == 0) {
#pragma unroll
        for (int i = 0; i < 4; ++i) {
            int row = warpM * 32 + (i >> 1) * 16 + (i & 1) * 8 + g;
            redM[warpN * 64 + row] = emax_run[i];
            redZ[warpN * 64 + row] = z_run[i];
        }
    }
    __syncthreads();
    if (tid < 64) {
        float em = redM[tid], z = redZ[tid];
#pragma unroll
        for (int w = 1; w < 4; ++w) {
            em = fmaxf(em, redM[w * 64 + tid]);
            z += redZ[w * 64 + tid];
        }
        float inv = 1.0f / (em + z);       // denom = e^m + sum e^s
        sInv[tid] = inv;
        pb[(size_t)tid * SP1] = 0.0f;      // sink: exp(-1e9 - m) == 0 in fp32
    }
    __syncthreads();

    // ---- write O (scaled) ----
#pragma unroll
    for (int mt = 0; mt < 2; ++mt)
#pragma unroll
        for (int rh = 0; rh < 2; ++rh) {
            int row = warpM * 32 + mt * 16 + rh * 8 + g;
            float inv = sInv[row];
#pragma unroll
            for (int nt = 0; nt < 4; ++nt) {
                int col = warpN * 32 + nt * 8 + tg * 2;
                float2 val = make_float2(oacc[mt][nt][rh * 2] * inv,
                                         oacc[mt][nt][rh * 2 + 1] * inv);
                *(float2*)(ob + (size_t)row * DD + col) = val;
            }
        }

    // ---- finalize p: read fp16 scratch, scale, alignment-phased writes ----
#pragma unroll 1
    for (int rr = 0; rr < 8; ++rr) {
        const int row = wid * 8 + rr;
        const float iv = sInv[row];
        const uint4* src = (const uint4*)(e_scratch + ((size_t)(gq + row) * SS >> 1));
        float* ga = pb + (size_t)row * SP1 + 1;
        const int h = (3 - row) & 3;
#pragma unroll 2
        for (int t = lane; t < 256; t += 32) {
            uint4 u = __ldcs(src + t);
            float2 f0 = __half22float2(*(__half2*)&u.x);
            float2 f1 = __half22float2(*(__half2*)&u.y);
            float2 f2 = __half22float2(*(__half2*)&u.z);
            float2 f3 = __half22float2(*(__half2*)&u.w);
            float v0 = f0.x * iv, v1 = f0.y * iv, v2 = f1.x * iv, v3 = f1.y * iv;
            float v4 = f2.x * iv, v5 = f2.y * iv, v6 = f3.x * iv, v7 = f3.y * iv;
            float* gp = ga + t * 8;
            if (h == 0) {
                *(float4*)gp       = make_float4(v0, v1, v2, v3);
                *(float4*)(gp + 4) = make_float4(v4, v5, v6, v7);
            } else if (h == 1) {
                gp[0] = v0;
                *(float4*)(gp + 1) = make_float4(v1, v2, v3, v4);
                *(float2*)(gp + 5) = make_float2(v5, v6);
                gp[7] = v7;
            } else if (h == 2) {
                *(float2*)gp       = make_float2(v0, v1);
                *(float4*)(gp + 2) = make_float4(v2, v3, v4, v5);
                *(float2*)(gp + 6) = make_float2(v6, v7);
            } else {
                gp[0] = v0;
                *(float2*)(gp + 1) = make_float2(v1, v2);
                *(float4*)(gp + 3) = make_float4(v3, v4, v5, v6);
                gp[7] = v7;
            }
        }
    }
}

extern "C" void kernel_launch(void* const* d_in, const int* in_sizes, int n_in,
                              void* d_out, int out_size)
{
    const float* q    = (const float*)d_in[0];
    const float* k    = (const float*)d_in[1];
    const float* v    = (const float*)d_in[2];
    const int*   mask = (const int*)d_in[3];

    const long OUT_N = (long)BB * SS * DD;
    const long P_N   = (long)BB * SS * SP1;

    float* out = (float*)d_out;
    float* p   = ((long)out_size == P_N) ? out : out + OUT_N;

    cudaFuncSetAttribute(qa_spA_kernel,
                         cudaFuncAttributeMaxDynamicSharedMemorySize, SMEM_TOTAL);
    dim3 grid(SS / TQ, BB);
    qa_spA_kernel<<<grid, NTH, SMEM_TOTAL>>>(q, k, v, mask, out, p);
}

// round 17
// speedup vs baseline: 1.4741x; 1.0523x over previous
#include <cuda_runtime.h>
#include <cuda_fp16.h>
#include <cstdint>

// QuietAttention, single-pass unnormalized softmax, TQ=64/TK=64,
// 256 threads, 2 CTAs/SM. QK: fp16 Q hi/lo x fp16 K single (pre-scaled)
// = 2 MMAs. PV: fp16 P x fp16 V (single). e staged fp16 via coalesced
// P-smem->scratch copy. out [16,2048,128] fp32 then p_attn fp32 in d_out.

#define BB 16
#define SS 2048
#define DD 128
#define SP1 2049
#define NTH 256
#define TQ 64
#define TK 64
#define PITCHB 272
#define PITCHP 144

#define OFF_QHI 0               // 64 x 272 = 17408
#define OFF_QLO 17408
#define OFF_K   34816           // K fp16 single; after QK reused as P
#define OFF_V   52224           // V fp16 single
#define OFF_MB  69632           // uint16 mbits[64][4] = 512
#define OFF_RM  70144
#define OFF_RZ  71168
#define OFF_SI  72192
#define SMEM_TOTAL 72448

// fp16 staging for unnormalized e: 16*2048*2048 halves = 128 MiB
static __device__ __half2 e_scratch[33554432];

__device__ __forceinline__ uint32_t smem_u32(const void* p) {
    uint32_t a;
    asm("{ .reg .u64 t; cvta.to.shared.u64 t, %1; cvt.u32.u64 %0, t; }" : "=r"(a) : "l"(p));
    return a;
}
__device__ __forceinline__ void pf_l2(const void* p) {
    asm volatile("prefetch.global.L2 [%0];" :: "l"(p));
}
__device__ __forceinline__ void ldsm4(uint32_t* r, uint32_t addr) {
    asm volatile("ldmatrix.sync.aligned.m8n8.x4.shared.b16 {%0,%1,%2,%3}, [%4];"
                 : "=r"(r[0]), "=r"(r[1]), "=r"(r[2]), "=r"(r[3]) : "r"(addr));
}
__device__ __forceinline__ void ldsm4t(uint32_t* r, uint32_t addr) {
    asm volatile("ldmatrix.sync.aligned.m8n8.x4.trans.shared.b16 {%0,%1,%2,%3}, [%4];"
                 : "=r"(r[0]), "=r"(r[1]), "=r"(r[2]), "=r"(r[3]) : "r"(addr));
}
__device__ __forceinline__ void mma_f16(float* c, const uint32_t* a, const uint32_t* b) {
    asm volatile("mma.sync.aligned.m16n8k16.row.col.f32.f16.f16.f32 "
                 "{%0,%1,%2,%3}, {%4,%5,%6,%7}, {%8,%9}, {%0,%1,%2,%3};"
                 : "+f"(c[0]), "+f"(c[1]), "+f"(c[2]), "+f"(c[3])
                 : "r"(a[0]), "r"(a[1]), "r"(a[2]), "r"(a[3]), "r"(b[0]), "r"(b[1]));
}
// fp16 hi/lo split
__device__ __forceinline__ void pack2h(float a, float b, uint32_t& h, uint32_t& l) {
    __half2 hh = __floats2half2_rn(a, b);
    float2 hf = __half22float2(hh);
    __half2 ll = __floats2half2_rn(a - hf.x, b - hf.y);
    h = *(uint32_t*)&hh; l = *(uint32_t*)&ll;
}

// 64x128 fp32 tile -> fp16 hi/lo smem (Q operand), STS.128
__device__ __forceinline__ void cvt_tile_hl(const float* __restrict__ src,
                                            char* hi, char* lo, int tid) {
#pragma unroll
    for (int it = 0; it < 4; ++it) {
        int n8  = tid + it * NTH;
        int row = n8 >> 4, c8 = n8 & 15;
        float4 x0 = ((const float4*)src)[n8 * 2];
        float4 x1 = ((const float4*)src)[n8 * 2 + 1];
        uint32_t h0, l0, h1, l1, h2, l2, h3, l3;
        pack2h(x0.x, x0.y, h0, l0);
        pack2h(x0.z, x0.w, h1, l1);
        pack2h(x1.x, x1.y, h2, l2);
        pack2h(x1.z, x1.w, h3, l3);
        *(uint4*)(hi + row * PITCHB + c8 * 16) = make_uint4(h0, h1, h2, h3);
        *(uint4*)(lo + row * PITCHB + c8 * 16) = make_uint4(l0, l1, l2, l3);
    }
}
// 64x128 fp32 tile -> fp16 single smem; optional compile-time pre-scale
template<bool SCALED>
__device__ __forceinline__ void cvt_tile_h1(const float* __restrict__ src,
                                            char* dst, int tid) {
    const float mul = 0.08838834764831845f;   // 1/sqrt(128)
#pragma unroll
    for (int it = 0; it < 4; ++it) {
        int n8  = tid + it * NTH;
        int row = n8 >> 4, c8 = n8 & 15;
        float4 x0 = ((const float4*)src)[n8 * 2];
        float4 x1 = ((const float4*)src)[n8 * 2 + 1];
        if (SCALED) {
            x0.x *= mul; x0.y *= mul; x0.z *= mul; x0.w *= mul;
            x1.x *= mul; x1.y *= mul; x1.z *= mul; x1.w *= mul;
        }
        __half2 p0 = __floats2half2_rn(x0.x, x0.y);
        __half2 p1 = __floats2half2_rn(x0.z, x0.w);
        __half2 p2 = __floats2half2_rn(x1.x, x1.y);
        __half2 p3 = __floats2half2_rn(x1.z, x1.w);
        *(uint4*)(dst + row * PITCHB + c8 * 16) =
            make_uint4(*(uint32_t*)&p0, *(uint32_t*)&p1, *(uint32_t*)&p2, *(uint32_t*)&p3);
    }
}

__global__ __launch_bounds__(NTH, 2)
void qa_spB_kernel(const float* __restrict__ q,
                   const float* __restrict__ k,
                   const float* __restrict__ v,
                   const int* __restrict__ mask,
                   float* __restrict__ out,
                   float* __restrict__ p)
{
    extern __shared__ char smem[];
    const uint32_t sb = smem_u32(smem);
    const int tid = threadIdx.x;
    const int lane = tid & 31, wid = tid >> 5;
    const int g = lane >> 2, tg = lane & 3;
    const int warpM = wid >> 2, warpN = wid & 3;
    const int b = blockIdx.y, qbase = blockIdx.x * TQ;
    const int gq = b * SS + qbase;

    const float* qb = q + (size_t)gq * DD;
    const float* kb = k + (size_t)b * SS * DD;
    const float* vb = v + (size_t)b * SS * DD;
    const int*   mk = mask + (size_t)gq * SS;
    float*       pb = p + (size_t)gq * SP1;
    float*       ob = out + (size_t)gq * DD;

    uint16_t* mbits = (uint16_t*)(smem + OFF_MB);
    float* redM = (float*)(smem + OFF_RM);
    float* redZ = (float*)(smem + OFF_RZ);
    float* sInv = (float*)(smem + OFF_SI);

    const uint32_t a_off  = (uint32_t)((((lane >> 3) & 1) * 8 + (lane & 7)) * PITCHB + (lane >> 4) * 16);
    const uint32_t b_off  = (uint32_t)(((lane >> 4) * 8 + (lane & 7)) * PITCHB + ((lane >> 3) & 1) * 16);
    const uint32_t a_offP = (uint32_t)((((lane >> 3) & 1) * 8 + (lane & 7)) * PITCHP + (lane >> 4) * 16);

    cvt_tile_hl(qb, smem + OFF_QHI, smem + OFF_QLO, tid);   // Q fp16 hi/lo
    pf_l2((const char*)kb + tid * 128);
    pf_l2((const char*)vb + tid * 128);
    pf_l2((const char*)(mk + (size_t)(tid >> 2) * SS + (tid & 3) * 16));

    float emax_run[4], z_run[4];
#pragma unroll
    for (int i = 0; i < 4; ++i) { emax_run[i] = 0.0f; z_run[i] = 0.0f; }

    float oacc[2][4][4];
#pragma unroll
    for (int mt = 0; mt < 2; ++mt)
#pragma unroll
        for (int nt = 0; nt < 4; ++nt)
#pragma unroll
            for (int e = 0; e < 4; ++e) oacc[mt][nt][e] = 0.0f;

    for (int kt = 0; kt < 32; ++kt) {
        __syncthreads();
        cvt_tile_h1<true>(kb + (size_t)kt * TK * DD, smem + OFF_K, tid);  // K pre-scaled
        {
            const int row = tid >> 2, cg = tid & 3;
            const int4* mp = (const int4*)(mk + (size_t)row * SS + kt * TK + cg * 16);
            uint32_t bits = 0;
#pragma unroll
            for (int j = 0; j < 4; ++j) {
                int4 m4 = __ldcs(mp + j);
                bits |= (m4.x ? 1u : 0u) << (4 * j);
                bits |= (m4.y ? 1u : 0u) << (4 * j + 1);
                bits |= (m4.z ? 1u : 0u) << (4 * j + 2);
                bits |= (m4.w ? 1u : 0u) << (4 * j + 3);
            }
            mbits[row * 4 + cg] = (uint16_t)bits;
        }
        __syncthreads();

        if (kt + 1 < 32) {
            pf_l2((const char*)(kb + (size_t)(kt + 1) * TK * DD) + tid * 128);
            pf_l2((const char*)(mk + (size_t)(tid >> 2) * SS + (kt + 1) * TK + (tid & 3) * 16));
        }

        // ---- S = Q K^T: Q fp16 hi/lo x K fp16 single, 2 split-MMAs ----
        float sacc[2][2][4];
#pragma unroll
        for (int mt = 0; mt < 2; ++mt)
#pragma unroll
            for (int nt = 0; nt < 2; ++nt)
#pragma unroll
                for (int e = 0; e < 4; ++e) sacc[mt][nt][e] = 0.0f;

#pragma unroll
        for (int ks = 0; ks < 8; ++ks) {
            uint32_t ah[2][4], al[2][4], bK[4];
#pragma unroll
            for (int mt = 0; mt < 2; ++mt) {
                uint32_t ra = (uint32_t)((warpM * 32 + mt * 16) * PITCHB + ks * 32) + a_off;
                ldsm4(ah[mt], sb + OFF_QHI + ra);
                ldsm4(al[mt], sb + OFF_QLO + ra);
            }
            ldsm4(bK, sb + OFF_K + (uint32_t)((warpN * 16) * PITCHB + ks * 32) + b_off);
            // split-outer: 4 independent accumulators between same-reg issues
#pragma unroll
            for (int mt = 0; mt < 2; ++mt)
#pragma unroll
                for (int nt = 0; nt < 2; ++nt)
                    mma_f16(sacc[mt][nt], ah[mt], &bK[nt * 2]);   // qh*k
#pragma unroll
            for (int mt = 0; mt < 2; ++mt)
#pragma unroll
                for (int nt = 0; nt < 2; ++nt)
                    mma_f16(sacc[mt][nt], al[mt], &bK[nt * 2]);   // ql*k
        }

        // ---- epilogue: e = exp(s) masked->0; stats only ----
#pragma unroll
        for (int mt = 0; mt < 2; ++mt) {
#pragma unroll
            for (int rh = 0; rh < 2; ++rh) {
                const int i = mt * 2 + rh;
                const int row = warpM * 32 + mt * 16 + rh * 8 + g;
                const uint32_t mw = mbits[row * 4 + warpN];
#pragma unroll
                for (int nt = 0; nt < 2; ++nt) {
                    int bit = nt * 8 + tg * 2;
                    float e0 = ((mw >> bit) & 1u)       ? __expf(sacc[mt][nt][rh * 2])     : 0.0f;
                    float e1 = ((mw >> (bit + 1)) & 1u) ? __expf(sacc[mt][nt][rh * 2 + 1]) : 0.0f;
                    emax_run[i] = fmaxf(emax_run[i], fmaxf(e0, e1));
                    z_run[i] += e0 + e1;
                    sacc[mt][nt][rh * 2]     = e0;
                    sacc[mt][nt][rh * 2 + 1] = e1;
                }
            }
        }

        __syncthreads();   // K smem reads done -> reuse as P (fp16, single)
        {
            char* pP = smem + OFF_K;
#pragma unroll
            for (int mt = 0; mt < 2; ++mt)
#pragma unroll
                for (int rh = 0; rh < 2; ++rh) {
                    const int row = warpM * 32 + mt * 16 + rh * 8 + g;
#pragma unroll
                    for (int nt = 0; nt < 2; ++nt) {
                        __half2 hv = __floats2half2_rn(sacc[mt][nt][rh * 2],
                                                       sacc[mt][nt][rh * 2 + 1]);
                        const int col = warpN * 16 + nt * 8 + tg * 2;
                        *(uint32_t*)(pP + row * PITCHP + col * 2) = *(uint32_t*)&hv;
                    }
                }
        }
        cvt_tile_h1<false>(vb + (size_t)kt * TK * DD, smem + OFF_V, tid);
        if (kt + 1 < 32)
            pf_l2((const char*)(vb + (size_t)(kt + 1) * TK * DD) + tid * 128);
        __syncthreads();

        // ---- coalesced P-smem -> scratch copy (overlaps PV) ----
        {
            const char* pP = smem + OFF_K;
#pragma unroll
            for (int it2 = 0; it2 < 2; ++it2) {
                int n = tid + it2 * NTH;
                int row = n >> 3, ch = n & 7;
                uint4 u = *(const uint4*)(pP + row * PITCHP + ch * 16);
                uint4* dst = (uint4*)(e_scratch + (size_t)(gq + row) * (SS / 2) + kt * (TK / 2)) + ch;
                __stcs(dst, u);
            }
        }

        // ---- O += P V: fp16 P single x fp16 V single ----
#pragma unroll
        for (int ks = 0; ks < 4; ++ks) {
            uint32_t ap[2][4], bh[2][4];
#pragma unroll
            for (int mt = 0; mt < 2; ++mt) {
                uint32_t ra = (uint32_t)((warpM * 32 + mt * 16) * PITCHP + ks * 32) + a_offP;
                ldsm4(ap[mt], sb + OFF_K + ra);
            }
#pragma unroll
            for (int n2 = 0; n2 < 2; ++n2) {
                uint32_t rb = (uint32_t)((ks * 16) * PITCHB + (warpN * 32 + n2 * 16) * 2) + a_off;
                ldsm4t(bh[n2], sb + OFF_V + rb);
            }
#pragma unroll
            for (int mt = 0; mt < 2; ++mt)
#pragma unroll
                for (int nt = 0; nt < 4; ++nt)
                    mma_f16(oacc[mt][nt], ap[mt], &bh[nt >> 1][(nt & 1) * 2]);
        }
    }

    // ---- reduce emax (max) and Z (sum) ----
#pragma unroll
    for (int off = 1; off <= 2; off <<= 1) {
#pragma unroll
        for (int i = 0; i < 4; ++i) {
            emax_run[i] = fmaxf(emax_run[i], __shfl_xor_sync(0xffffffffu, emax_run[i], off));
            z_run[i] += __shfl_xor_sync(0xffffffffu, z_run[i], off);
        }
    }
    __syncthreads();
    if (tg == 0) {
#pragma unroll
        for (int i = 0; i < 4; ++i) {
            int row = warpM * 32 + (i >> 1) * 16 + (i & 1) * 8 + g;
            redM[warpN * 64 + row] = emax_run[i];
            redZ[warpN * 64 + row] = z_run[i];
        }
    }
    __syncthreads();
    if (tid < 64) {
        float em = redM[tid], z = redZ[tid];
#pragma unroll
        for (int w = 1; w < 4; ++w) {
            em = fmaxf(em, redM[w * 64 + tid]);
            z += redZ[w * 64 + tid];
        }
        float inv = 1.0f / (em + z);       // denom = e^m + sum e^s
        sInv[tid] = inv;
        pb[(size_t)tid * SP1] = 0.0f;      // sink: exp(-1e9 - m) == 0 in fp32
    }
    __syncthreads();

    // ---- write O (scaled) ----
#pragma unroll
    for (int mt = 0; mt < 2; ++mt)
#pragma unroll
        for (int rh = 0; rh < 2; ++rh) {
            int row = warpM * 32 + mt * 16 + rh * 8 + g;
            float inv = sInv[row];
#pragma unroll
            for (int nt = 0; nt < 4; ++nt) {
                int col = warpN * 32 + nt * 8 + tg * 2;
                float2 val = make_float2(oacc[mt][nt][rh * 2] * inv,
                                         oacc[mt][nt][rh * 2 + 1] * inv);
                *(float2*)(ob + (size_t)row * DD + col) = val;
            }
        }

    // ---- finalize p: read fp16 scratch, scale, alignment-phased writes ----
#pragma unroll 1
    for (int rr = 0; rr < 8; ++rr) {
        const int row = wid * 8 + rr;
        const float iv = sInv[row];
        const uint4* src = (const uint4*)(e_scratch + ((size_t)(gq + row) * SS >> 1));
        float* ga = pb + (size_t)row * SP1 + 1;
        const int h = (3 - row) & 3;
#pragma unroll 2
        for (int t = lane; t < 256; t += 32) {
            uint4 u = __ldcs(src + t);
            float2 f0 = __half22float2(*(__half2*)&u.x);
            float2 f1 = __half22float2(*(__half2*)&u.y);
            float2 f2 = __half22float2(*(__half2*)&u.z);
            float2 f3 = __half22float2(*(__half2*)&u.w);
            float v0 = f0.x * iv, v1 = f0.y * iv, v2 = f1.x * iv, v3 = f1.y * iv;
            float v4 = f2.x * iv, v5 = f2.y * iv, v6 = f3.x * iv, v7 = f3.y * iv;
            float* gp = ga + t * 8;
            if (h == 0) {
                *(float4*)gp       = make_float4(v0, v1, v2, v3);
                *(float4*)(gp + 4) = make_float4(v4, v5, v6, v7);
            } else if (h == 1) {
                gp[0] = v0;
                *(float4*)(gp + 1) = make_float4(v1, v2, v3, v4);
                *(float2*)(gp + 5) = make_float2(v5, v6);
                gp[7] = v7;
            } else if (h == 2) {
                *(float2*)gp       = make_float2(v0, v1);
                *(float4*)(gp + 2) = make_float4(v2, v3, v4, v5);
                *(float2*)(gp + 6) = make_float2(v6, v7);
            } else {
                gp[0] = v0;
                *(float2*)(gp + 1) = make_float2(v1, v2);
                *(float4*)(gp + 3) = make_float4(v3, v4, v5, v6);
                gp[7] = v7;
            }
        }
    }
}

extern "C" void kernel_launch(void* const* d_in, const int* in_sizes, int n_in,
                              void* d_out, int out_size)
{
    const float* q    = (const float*)d_in[0];
    const float* k    = (const float*)d_in[1];
    const float* v    = (const float*)d_in[2];
    const int*   mask = (const int*)d_in[3];

    const long OUT_N = (long)BB * SS * DD;
    const long P_N   = (long)BB * SS * SP1;

    float* out = (float*)d_out;
    float* p   = ((long)out_size == P_N) ? out : out + OUT_N;

    cudaFuncSetAttribute(qa_spB_kernel,
                         cudaFuncAttributeMaxDynamicSharedMemorySize, SMEM_TOTAL);
    dim3 grid(SS / TQ, BB);
    qa_spB_kernel<<<grid, NTH, SMEM_TOTAL>>>(q, k, v, mask, out, p);
}